// round 4
// baseline (speedup 1.0000x reference)
#include <cuda_runtime.h>
#include <cuda_bf16.h>
#include <cstdint>

// Problem constants
#define BATCH 2
#define SEQ   2048
#define HID   1024
#define NHEAD 16
#define HDIM  64
#define ROWS  (BATCH * SEQ)      // 4096
#define KSP   2048               // split storage width: [hi | lo]
#define NQKV  3072               // fused QKV output width
#define NIT   96                 // 96 k-chunks of 32 (virtual K = 3072)

// ---------------- scratch (static device allocations; no cudaMalloc) --------
__device__ __nv_bfloat16 g_hs   [ROWS * KSP];   // h split [hi|lo]
__device__ __nv_bfloat16 g_Wqkvs[NQKV * KSP];   // [Wq;Wk;Wv] split
__device__ __nv_bfloat16 g_Wos  [HID  * KSP];
__device__ __nv_bfloat16 g_ATTs [ROWS * KSP];   // attention out, split (written by qs)
__device__ float g_QKV[ROWS * NQKV];            // fused projections (fp32)
__device__ float g_S  [BATCH * NHEAD * HDIM * HDIM];

// ---------------- helpers ----------------------------------------------------
__device__ __forceinline__ uint32_t smem_u32(const void* p) {
    uint32_t a;
    asm("{ .reg .u64 t; cvta.to.shared.u64 t, %1; cvt.u32.u64 %0, t; }"
        : "=r"(a) : "l"(p));
    return a;
}
__device__ __forceinline__ void cp16(uint32_t dst, const void* src) {
    asm volatile("cp.async.cg.shared.global [%0], [%1], 16;"
                 :: "r"(dst), "l"(src));
}

// ---------------- split: X fp32 [rows,1024] -> Y bf16 [rows, 2048]=[hi|lo] ---
__global__ void split_kernel(const float* __restrict__ X,
                             __nv_bfloat16* __restrict__ Y, int rows) {
    int i = blockIdx.x * 256 + threadIdx.x;
    if (i >= rows * 256) return;
    int r = i >> 8;
    int c4 = (i & 255) * 4;
    float4 v = *(const float4*)(X + (size_t)r * HID + c4);
    float f[4] = {v.x, v.y, v.z, v.w};
    unsigned sh[4], sl[4];
#pragma unroll
    for (int j = 0; j < 4; ++j) {
        __nv_bfloat16 hb = __float2bfloat16(f[j]);
        float hf = __bfloat162float(hb);
        __nv_bfloat16 lb = __float2bfloat16(f[j] - hf);
        sh[j] = (unsigned)__bfloat16_as_ushort(hb);
        sl[j] = (unsigned)__bfloat16_as_ushort(lb);
    }
    uint2 ph = make_uint2(sh[0] | (sh[1] << 16), sh[2] | (sh[3] << 16));
    uint2 pl = make_uint2(sl[0] | (sl[1] << 16), sl[2] | (sl[3] << 16));
    unsigned short* yb = (unsigned short*)Y + (size_t)r * KSP;
    *(uint2*)(yb + c4)       = ph;
    *(uint2*)(yb + HID + c4) = pl;
}

// ---------------- bf16-split GEMM via mma.sync (m16n8k16) -------------------
// C[4096, N] fp32 = A2[4096,2048] x B2[N,2048]^T over virtual K=3072:
//   chunk it (32 wide): term = it/32; A uses lo iff term==2, B lo iff term==1.
// Tile 128x256, 8 warps (2m x 4n), warp tile 64x64, 3-stage cp.async.
// Smem rows padded to 80B (64B data) -> conflict-free ldmatrix.
#define LDB    80                // smem row stride bytes
#define ASZ    10240             // 128*80  A tile bytes
#define STAGE  30720             // (128+256)*80
#define GSMEM  (3 * STAGE)       // 92160

__global__ __launch_bounds__(256, 1)
void gemm_bf16(const __nv_bfloat16* __restrict__ A,
               const __nv_bfloat16* __restrict__ B,
               float* __restrict__ C, int N) {
    extern __shared__ char sm[];
    const int tid = threadIdx.x, lane = tid & 31, wid = tid >> 5;
    const int wm = wid & 1, wn = wid >> 1;
    const int bm = blockIdx.y * 128, bn = blockIdx.x * 256;
    const uint32_t sb = smem_u32(sm);
    const char* Ag = (const char*)A + (size_t)bm * (KSP * 2);
    const char* Bg = (const char*)B + (size_t)bn * (KSP * 2);

    float acc[4][8][4];
#pragma unroll
    for (int mt = 0; mt < 4; ++mt)
#pragma unroll
        for (int nt = 0; nt < 8; ++nt)
#pragma unroll
            for (int j = 0; j < 4; ++j) acc[mt][nt][j] = 0.0f;

    const int lr = tid >> 2, lc = (tid & 3) * 16;

    auto load_stage = [&](int it) {
        int s = it % 3;
        int term = it >> 5, kk = (it & 31) * 32;
        int ak = ((term == 2) ? 1024 : 0) + kk;
        int bk = ((term == 1) ? 1024 : 0) + kk;
        uint32_t da = sb + s * STAGE, db = da + ASZ;
        const char* Ap = Ag + ak * 2;
        const char* Bp = Bg + bk * 2;
        cp16(da + lr * LDB + lc,        Ap + (size_t)lr * 4096 + lc);
        cp16(da + (lr + 64) * LDB + lc, Ap + (size_t)(lr + 64) * 4096 + lc);
#pragma unroll
        for (int t = 0; t < 4; ++t)
            cp16(db + (lr + t * 64) * LDB + lc,
                 Bp + (size_t)(lr + t * 64) * 4096 + lc);
        asm volatile("cp.async.commit_group;" ::: "memory");
    };

    load_stage(0);
    load_stage(1);

    for (int it = 0; it < NIT; ++it) {
        if (it < NIT - 1) asm volatile("cp.async.wait_group 1;" ::: "memory");
        else              asm volatile("cp.async.wait_group 0;" ::: "memory");
        __syncthreads();
        if (it + 2 < NIT) load_stage(it + 2);

        int s = it % 3;
        uint32_t abase = sb + s * STAGE +
                         (wm * 64 + (lane & 15)) * LDB + ((lane >> 4) & 1) * 16;
        uint32_t bbase = sb + s * STAGE + ASZ +
                         (wn * 64 + (lane & 7) + ((lane >> 3) & 1) * 8) * LDB +
                         ((lane >> 4) & 1) * 16;
#pragma unroll
        for (int ks = 0; ks < 2; ++ks) {
            uint32_t a[4][4], b[8][2];
#pragma unroll
            for (int mt = 0; mt < 4; ++mt)
                asm volatile(
                    "ldmatrix.sync.aligned.m8n8.x4.shared.b16 {%0,%1,%2,%3}, [%4];"
                    : "=r"(a[mt][0]), "=r"(a[mt][1]), "=r"(a[mt][2]), "=r"(a[mt][3])
                    : "r"(abase + ks * 32 + mt * (16 * LDB)));
#pragma unroll
            for (int g = 0; g < 4; ++g)
                asm volatile(
                    "ldmatrix.sync.aligned.m8n8.x4.shared.b16 {%0,%1,%2,%3}, [%4];"
                    : "=r"(b[2 * g][0]), "=r"(b[2 * g + 1][0]),
                      "=r"(b[2 * g][1]), "=r"(b[2 * g + 1][1])
                    : "r"(bbase + ks * 32 + g * (16 * LDB)));
#pragma unroll
            for (int mt = 0; mt < 4; ++mt)
#pragma unroll
                for (int nt = 0; nt < 8; ++nt)
                    asm volatile(
                        "mma.sync.aligned.m16n8k16.row.col.f32.bf16.bf16.f32 "
                        "{%0,%1,%2,%3}, {%4,%5,%6,%7}, {%8,%9}, {%0,%1,%2,%3};"
                        : "+f"(acc[mt][nt][0]), "+f"(acc[mt][nt][1]),
                          "+f"(acc[mt][nt][2]), "+f"(acc[mt][nt][3])
                        : "r"(a[mt][0]), "r"(a[mt][1]), "r"(a[mt][2]), "r"(a[mt][3]),
                          "r"(b[nt][0]), "r"(b[nt][1]));
        }
    }

    // epilogue: direct float2 stores (C fragment layout)
#pragma unroll
    for (int mt = 0; mt < 4; ++mt)
#pragma unroll
        for (int nt = 0; nt < 8; ++nt) {
            int r0 = bm + wm * 64 + mt * 16 + (lane >> 2);
            int c0 = bn + wn * 64 + nt * 8 + (lane & 3) * 2;
            *(float2*)(C + (size_t)r0 * N + c0) =
                make_float2(acc[mt][nt][0], acc[mt][nt][1]);
            *(float2*)(C + (size_t)(r0 + 8) * N + c0) =
                make_float2(acc[mt][nt][2], acc[mt][nt][3]);
        }
}

// ---------------- zero S ----------------------------------------------------
__global__ void zero_kernel(float* __restrict__ p, int n) {
    int i = blockIdx.x * blockDim.x + threadIdx.x;
    if (i < n) p[i] = 0.0f;
}

// ---------------- S[b,h] = K_h^T @ V_h  (64x64, reduce over SEQ) ------------
#define MSPLIT 8
#define MCHUNK (SEQ / MSPLIT)   // 256

__global__ __launch_bounds__(256)
void ktv_kernel() {
    const int bh = blockIdx.x;
    const int b  = bh / NHEAD;
    const int h  = bh % NHEAD;
    const int mbase = blockIdx.y * MCHUNK;

    __shared__ float Ks[16][HDIM];
    __shared__ float Vs[16][HDIM];

    const int tid = threadIdx.x;
    const int t1 = (tid >> 4) * 4;
    const int t2 = (tid & 15) * 4;

    const float* Kb = g_QKV + ((size_t)b * SEQ) * NQKV + HID + h * HDIM;
    const float* Vb = g_QKV + ((size_t)b * SEQ) * NQKV + 2 * HID + h * HDIM;

    float acc[4][4];
#pragma unroll
    for (int i = 0; i < 4; ++i)
#pragma unroll
        for (int j = 0; j < 4; ++j) acc[i][j] = 0.0f;

    const int lrow = tid >> 4;
    const int lc4  = (tid & 15) * 4;

    for (int m0 = mbase; m0 < mbase + MCHUNK; m0 += 16) {
        float4 kv = *(const float4*)(Kb + (size_t)(m0 + lrow) * NQKV + lc4);
        float4 vv = *(const float4*)(Vb + (size_t)(m0 + lrow) * NQKV + lc4);
        *(float4*)&Ks[lrow][lc4] = kv;
        *(float4*)&Vs[lrow][lc4] = vv;
        __syncthreads();
#pragma unroll
        for (int m = 0; m < 16; ++m) {
            float a[4], v[4];
#pragma unroll
            for (int i = 0; i < 4; ++i) a[i] = Ks[m][t1 + i];
#pragma unroll
            for (int j = 0; j < 4; ++j) v[j] = Vs[m][t2 + j];
#pragma unroll
            for (int i = 0; i < 4; ++i)
#pragma unroll
                for (int j = 0; j < 4; ++j)
                    acc[i][j] = fmaf(a[i], v[j], acc[i][j]);
        }
        __syncthreads();
    }

    float* Sb = g_S + (size_t)bh * HDIM * HDIM;
#pragma unroll
    for (int i = 0; i < 4; ++i)
#pragma unroll
        for (int j = 0; j < 4; ++j)
            atomicAdd(&Sb[(t1 + i) * HDIM + t2 + j], acc[i][j]);
}

// -------- A[b,h] = Q_h @ S[b,h]  -> g_ATTs (fused bf16 hi/lo split) ---------
__global__ __launch_bounds__(256)
void qs_kernel() {
    const int bh = blockIdx.x;
    const int b  = bh / NHEAD;
    const int h  = bh % NHEAD;
    const int m0 = blockIdx.y * 128;

    __shared__ float Ss[HDIM][HDIM];
    __shared__ float Qs[16][128];

    const int tid = threadIdx.x;

    {
        const float* Sb = g_S + (size_t)bh * HDIM * HDIM;
#pragma unroll
        for (int it = 0; it < 4; ++it) {
            int idx = tid + it * 256;
            int row = idx >> 4;
            int c4  = (idx & 15) * 4;
            *(float4*)&Ss[row][c4] = *(const float4*)(Sb + row * HDIM + c4);
        }
    }

    const int ty = tid >> 3;
    const int tx = tid & 7;

    float acc[4][8];
#pragma unroll
    for (int i = 0; i < 4; ++i)
#pragma unroll
        for (int j = 0; j < 8; ++j) acc[i][j] = 0.0f;

    const float* Qb = g_QKV + ((size_t)b * SEQ + m0) * NQKV + h * HDIM;

    for (int kb = 0; kb < 4; ++kb) {
        const int k0 = kb * 16;
#pragma unroll
        for (int it = 0; it < 2; ++it) {
            int idx = tid + it * 256;
            int row = idx >> 2;
            int kq  = (idx & 3) * 4;
            float4 v = *(const float4*)(Qb + (size_t)row * NQKV + k0 + kq);
            Qs[kq + 0][row] = v.x;
            Qs[kq + 1][row] = v.y;
            Qs[kq + 2][row] = v.z;
            Qs[kq + 3][row] = v.w;
        }
        __syncthreads();
#pragma unroll
        for (int kk = 0; kk < 16; ++kk) {
            float q[4], s[8];
#pragma unroll
            for (int i = 0; i < 4; ++i) q[i] = Qs[kk][ty * 4 + i];
            float4 s0 = *(const float4*)&Ss[k0 + kk][tx * 8];
            float4 s1 = *(const float4*)&Ss[k0 + kk][tx * 8 + 4];
            s[0]=s0.x; s[1]=s0.y; s[2]=s0.z; s[3]=s0.w;
            s[4]=s1.x; s[5]=s1.y; s[6]=s1.z; s[7]=s1.w;
#pragma unroll
            for (int i = 0; i < 4; ++i)
#pragma unroll
                for (int j = 0; j < 8; ++j)
                    acc[i][j] = fmaf(q[i], s[j], acc[i][j]);
        }
        __syncthreads();
    }

    // fused split epilogue: write bf16 hi/lo directly
#pragma unroll
    for (int i = 0; i < 4; ++i) {
        unsigned sh[8], sl[8];
#pragma unroll
        for (int j = 0; j < 8; ++j) {
            float f = acc[i][j];
            __nv_bfloat16 hb = __float2bfloat16(f);
            float hf = __bfloat162float(hb);
            __nv_bfloat16 lb = __float2bfloat16(f - hf);
            sh[j] = (unsigned)__bfloat16_as_ushort(hb);
            sl[j] = (unsigned)__bfloat16_as_ushort(lb);
        }
        uint4 ph = make_uint4(sh[0] | (sh[1] << 16), sh[2] | (sh[3] << 16),
                              sh[4] | (sh[5] << 16), sh[6] | (sh[7] << 16));
        uint4 pl = make_uint4(sl[0] | (sl[1] << 16), sl[2] | (sl[3] << 16),
                              sl[4] | (sl[5] << 16), sl[6] | (sl[7] << 16));
        unsigned short* dst = (unsigned short*)g_ATTs +
            ((size_t)b * SEQ + m0 + ty * 4 + i) * KSP + h * HDIM + tx * 8;
        *(uint4*)dst          = ph;
        *(uint4*)(dst + HID)  = pl;   // lo block at column offset 1024
    }
}

// ---------------- launch ----------------------------------------------------
extern "C" void kernel_launch(void* const* d_in, const int* in_sizes, int n_in,
                              void* d_out, int out_size) {
    (void)in_sizes; (void)n_in; (void)out_size;
    const float* h   = (const float*)d_in[0];
    const float* Wq  = (const float*)d_in[1];
    const float* Wk  = (const float*)d_in[2];
    const float* Wv  = (const float*)d_in[3];
    // d_in[4] = Wspan (dead code in reference)
    const float* Wo  = (const float*)d_in[5];
    float* out = (float*)d_out;

    __nv_bfloat16 *pHs, *pWqkvs, *pWos, *pATTs;
    float *pQKV, *pS;
    cudaGetSymbolAddress((void**)&pHs,    g_hs);
    cudaGetSymbolAddress((void**)&pWqkvs, g_Wqkvs);
    cudaGetSymbolAddress((void**)&pWos,   g_Wos);
    cudaGetSymbolAddress((void**)&pATTs,  g_ATTs);
    cudaGetSymbolAddress((void**)&pQKV,   g_QKV);
    cudaGetSymbolAddress((void**)&pS,     g_S);

    cudaFuncSetAttribute(gemm_bf16,
                         cudaFuncAttributeMaxDynamicSharedMemorySize, GSMEM);

    // 1) split inputs to bf16 [hi|lo]
    split_kernel<<<ROWS, 256>>>(h,  pHs, ROWS);
    split_kernel<<<HID,  256>>>(Wq, pWqkvs,                          HID);
    split_kernel<<<HID,  256>>>(Wk, pWqkvs + (size_t)HID * KSP,      HID);
    split_kernel<<<HID,  256>>>(Wv, pWqkvs + (size_t)2 * HID * KSP,  HID);
    split_kernel<<<HID,  256>>>(Wo, pWos, HID);

    // 2) fused QKV projection on tensor cores (tile 128x256)
    gemm_bf16<<<dim3(NQKV / 256, ROWS / 128), 256, GSMEM>>>(pHs, pWqkvs, pQKV, NQKV);

    // 3) attention via associativity: ATT = Q (K^T V), split fused into qs
    int nS = BATCH * NHEAD * HDIM * HDIM;
    zero_kernel<<<(nS + 255) / 256, 256>>>(pS, nS);
    ktv_kernel<<<dim3(BATCH * NHEAD, MSPLIT), 256>>>();
    qs_kernel<<<dim3(BATCH * NHEAD, SEQ / 128), 256>>>();

    // 4) output projection
    gemm_bf16<<<dim3(HID / 256, ROWS / 128), 256, GSMEM>>>(pATTs, pWos, out, HID);
}

// round 5
// speedup vs baseline: 1.3979x; 1.3979x over previous
#include <cuda_runtime.h>
#include <cuda_fp16.h>
#include <cstdint>

// Problem constants
#define BATCH 2
#define SEQ   2048
#define HID   1024
#define NHEAD 16
#define HDIM  64
#define ROWS  (BATCH * SEQ)      // 4096
#define KSP   2048               // A-split storage width: [hi | lo]
#define NQKV  3072               // fused QKV output width
#define NIT   64                 // 64 k-chunks of 32 (virtual K = 2048)

// ---------------- scratch (static device allocations; no cudaMalloc) --------
__device__ __half g_hs   [ROWS * KSP];   // h split [hi|lo] fp16
__device__ __half g_Wqkvh[NQKV * HID];   // [Wq;Wk;Wv] hi fp16
__device__ __half g_Woh  [HID  * HID];   // Wo hi fp16
__device__ __half g_ATTs [ROWS * KSP];   // attention out split [hi|lo] fp16
__device__ float g_QKV[ROWS * NQKV];     // fused projections (fp32)
__device__ float g_S  [BATCH * NHEAD * HDIM * HDIM];

// ---------------- helpers ----------------------------------------------------
__device__ __forceinline__ uint32_t smem_u32(const void* p) {
    uint32_t a;
    asm("{ .reg .u64 t; cvta.to.shared.u64 t, %1; cvt.u32.u64 %0, t; }"
        : "=r"(a) : "l"(p));
    return a;
}
__device__ __forceinline__ void cp16(uint32_t dst, const void* src) {
    asm volatile("cp.async.cg.shared.global [%0], [%1], 16;"
                 :: "r"(dst), "l"(src));
}

// ---- split: X fp32 [rows,1024] -> Y fp16 [rows,2048]=[hi|lo] ---------------
__global__ void split16_kernel(const float* __restrict__ X,
                               __half* __restrict__ Y, int rows) {
    int i = blockIdx.x * 256 + threadIdx.x;
    if (i >= rows * 256) return;
    int r = i >> 8;
    int c4 = (i & 255) * 4;
    float4 v = *(const float4*)(X + (size_t)r * HID + c4);
    float f[4] = {v.x, v.y, v.z, v.w};
    unsigned sh[4], sl[4];
#pragma unroll
    for (int j = 0; j < 4; ++j) {
        __half hb = __float2half_rn(f[j]);
        float hf = __half2float(hb);
        __half lb = __float2half_rn(f[j] - hf);
        sh[j] = (unsigned)__half_as_ushort(hb);
        sl[j] = (unsigned)__half_as_ushort(lb);
    }
    uint2 ph = make_uint2(sh[0] | (sh[1] << 16), sh[2] | (sh[3] << 16));
    uint2 pl = make_uint2(sl[0] | (sl[1] << 16), sl[2] | (sl[3] << 16));
    unsigned short* yb = (unsigned short*)Y + (size_t)r * KSP;
    *(uint2*)(yb + c4)       = ph;
    *(uint2*)(yb + HID + c4) = pl;
}

// ---- convert: X fp32 [rows,1024] -> Y fp16 [rows,1024] (hi only) -----------
__global__ void cvt16_kernel(const float* __restrict__ X,
                             __half* __restrict__ Y, int rows) {
    int i = blockIdx.x * 256 + threadIdx.x;
    if (i >= rows * 256) return;
    float4 v = *(const float4*)(X + (size_t)i * 4);
    unsigned s0 = __half_as_ushort(__float2half_rn(v.x));
    unsigned s1 = __half_as_ushort(__float2half_rn(v.y));
    unsigned s2 = __half_as_ushort(__float2half_rn(v.z));
    unsigned s3 = __half_as_ushort(__float2half_rn(v.w));
    *(uint2*)((unsigned short*)Y + (size_t)i * 4) =
        make_uint2(s0 | (s1 << 16), s2 | (s3 << 16));
}

// ---------------- fp16 2-term GEMM via mma.sync (m16n8k16) ------------------
// C[4096, N] fp32 = (A_hi + A_lo)[4096,2048] x B_hi[N,1024]^T, virtual K=2048:
//   chunk it: term = it/32 (0: A hi cols, 1: A lo cols); B chunk = it%32 always.
// Tile 128x128, 8 warps (2m x 4n), warp tile 64x32, 3-stage cp.async.
// Smem rows padded to 80B (64B data) -> conflict-free ldmatrix.
#define LDB    80                // smem row stride bytes
#define ASZ    10240             // 128*80 per tile
#define STAGE  20480             // A + B
#define GSMEM  (3 * STAGE)       // 61440

__global__ __launch_bounds__(256, 2)
void gemm_fp16(const __half* __restrict__ A,
               const __half* __restrict__ B,
               float* __restrict__ C, int N) {
    extern __shared__ char sm[];
    const int tid = threadIdx.x, lane = tid & 31, wid = tid >> 5;
    const int wm = wid & 1, wn = wid >> 1;
    const int bm = blockIdx.y * 128, bn = blockIdx.x * 128;
    const uint32_t sb = smem_u32(sm);
    const char* Ag = (const char*)A + (size_t)bm * (KSP * 2);
    const char* Bg = (const char*)B + (size_t)bn * (HID * 2);

    float acc[4][4][4];
#pragma unroll
    for (int mt = 0; mt < 4; ++mt)
#pragma unroll
        for (int nt = 0; nt < 4; ++nt)
#pragma unroll
            for (int j = 0; j < 4; ++j) acc[mt][nt][j] = 0.0f;

    const int lr = tid >> 2, lc = (tid & 3) * 16;

    auto load_stage = [&](int it) {
        int s = it % 3;
        int kk = (it & 31) * 32;
        int ak = ((it >> 5) ? 1024 : 0) + kk;
        uint32_t da = sb + s * STAGE, db = da + ASZ;
        const char* Ap = Ag + ak * 2;
        const char* Bp = Bg + kk * 2;
        cp16(da + lr * LDB + lc,        Ap + (size_t)lr * 4096 + lc);
        cp16(da + (lr + 64) * LDB + lc, Ap + (size_t)(lr + 64) * 4096 + lc);
        cp16(db + lr * LDB + lc,        Bp + (size_t)lr * 2048 + lc);
        cp16(db + (lr + 64) * LDB + lc, Bp + (size_t)(lr + 64) * 2048 + lc);
        asm volatile("cp.async.commit_group;" ::: "memory");
    };

    load_stage(0);
    load_stage(1);

    for (int it = 0; it < NIT; ++it) {
        if (it < NIT - 1) asm volatile("cp.async.wait_group 1;" ::: "memory");
        else              asm volatile("cp.async.wait_group 0;" ::: "memory");
        __syncthreads();
        if (it + 2 < NIT) load_stage(it + 2);

        int s = it % 3;
        uint32_t abase = sb + s * STAGE +
                         (wm * 64 + (lane & 15)) * LDB + ((lane >> 4) & 1) * 16;
        uint32_t bbase = sb + s * STAGE + ASZ +
                         (wn * 32 + (lane & 7) + ((lane >> 3) & 1) * 8) * LDB +
                         ((lane >> 4) & 1) * 16;
#pragma unroll
        for (int ks = 0; ks < 2; ++ks) {
            uint32_t a[4][4], b[4][2];
#pragma unroll
            for (int mt = 0; mt < 4; ++mt)
                asm volatile(
                    "ldmatrix.sync.aligned.m8n8.x4.shared.b16 {%0,%1,%2,%3}, [%4];"
                    : "=r"(a[mt][0]), "=r"(a[mt][1]), "=r"(a[mt][2]), "=r"(a[mt][3])
                    : "r"(abase + ks * 32 + mt * (16 * LDB)));
#pragma unroll
            for (int g = 0; g < 2; ++g)
                asm volatile(
                    "ldmatrix.sync.aligned.m8n8.x4.shared.b16 {%0,%1,%2,%3}, [%4];"
                    : "=r"(b[2 * g][0]), "=r"(b[2 * g + 1][0]),
                      "=r"(b[2 * g][1]), "=r"(b[2 * g + 1][1])
                    : "r"(bbase + ks * 32 + g * (16 * LDB)));
#pragma unroll
            for (int mt = 0; mt < 4; ++mt)
#pragma unroll
                for (int nt = 0; nt < 4; ++nt)
                    asm volatile(
                        "mma.sync.aligned.m16n8k16.row.col.f32.f16.f16.f32 "
                        "{%0,%1,%2,%3}, {%4,%5,%6,%7}, {%8,%9}, {%0,%1,%2,%3};"
                        : "+f"(acc[mt][nt][0]), "+f"(acc[mt][nt][1]),
                          "+f"(acc[mt][nt][2]), "+f"(acc[mt][nt][3])
                        : "r"(a[mt][0]), "r"(a[mt][1]), "r"(a[mt][2]), "r"(a[mt][3]),
                          "r"(b[nt][0]), "r"(b[nt][1]));
        }
    }

    // epilogue: direct float2 stores (C fragment layout)
#pragma unroll
    for (int mt = 0; mt < 4; ++mt)
#pragma unroll
        for (int nt = 0; nt < 4; ++nt) {
            int r0 = bm + wm * 64 + mt * 16 + (lane >> 2);
            int c0 = bn + wn * 32 + nt * 8 + (lane & 3) * 2;
            *(float2*)(C + (size_t)r0 * N + c0) =
                make_float2(acc[mt][nt][0], acc[mt][nt][1]);
            *(float2*)(C + (size_t)(r0 + 8) * N + c0) =
                make_float2(acc[mt][nt][2], acc[mt][nt][3]);
        }
}

// ---------------- zero S ----------------------------------------------------
__global__ void zero_kernel(float* __restrict__ p, int n) {
    int i = blockIdx.x * blockDim.x + threadIdx.x;
    if (i < n) p[i] = 0.0f;
}

// ---------------- S[b,h] = K_h^T @ V_h  (64x64, reduce over SEQ) ------------
#define MSPLIT 8
#define MCHUNK (SEQ / MSPLIT)   // 256

__global__ __launch_bounds__(256)
void ktv_kernel() {
    const int bh = blockIdx.x;
    const int b  = bh / NHEAD;
    const int h  = bh % NHEAD;
    const int mbase = blockIdx.y * MCHUNK;

    __shared__ float Ks[16][HDIM];
    __shared__ float Vs[16][HDIM];

    const int tid = threadIdx.x;
    const int t1 = (tid >> 4) * 4;
    const int t2 = (tid & 15) * 4;

    const float* Kb = g_QKV + ((size_t)b * SEQ) * NQKV + HID + h * HDIM;
    const float* Vb = g_QKV + ((size_t)b * SEQ) * NQKV + 2 * HID + h * HDIM;

    float acc[4][4];
#pragma unroll
    for (int i = 0; i < 4; ++i)
#pragma unroll
        for (int j = 0; j < 4; ++j) acc[i][j] = 0.0f;

    const int lrow = tid >> 4;
    const int lc4  = (tid & 15) * 4;

    for (int m0 = mbase; m0 < mbase + MCHUNK; m0 += 16) {
        float4 kv = *(const float4*)(Kb + (size_t)(m0 + lrow) * NQKV + lc4);
        float4 vv = *(const float4*)(Vb + (size_t)(m0 + lrow) * NQKV + lc4);
        *(float4*)&Ks[lrow][lc4] = kv;
        *(float4*)&Vs[lrow][lc4] = vv;
        __syncthreads();
#pragma unroll
        for (int m = 0; m < 16; ++m) {
            float a[4], v[4];
#pragma unroll
            for (int i = 0; i < 4; ++i) a[i] = Ks[m][t1 + i];
#pragma unroll
            for (int j = 0; j < 4; ++j) v[j] = Vs[m][t2 + j];
#pragma unroll
            for (int i = 0; i < 4; ++i)
#pragma unroll
                for (int j = 0; j < 4; ++j)
                    acc[i][j] = fmaf(a[i], v[j], acc[i][j]);
        }
        __syncthreads();
    }

    float* Sb = g_S + (size_t)bh * HDIM * HDIM;
#pragma unroll
    for (int i = 0; i < 4; ++i)
#pragma unroll
        for (int j = 0; j < 4; ++j)
            atomicAdd(&Sb[(t1 + i) * HDIM + t2 + j], acc[i][j]);
}

// -------- A[b,h] = Q_h @ S[b,h]  -> g_ATTs (fused fp16 hi/lo split) ---------
__global__ __launch_bounds__(256)
void qs_kernel() {
    const int bh = blockIdx.x;
    const int b  = bh / NHEAD;
    const int h  = bh % NHEAD;
    const int m0 = blockIdx.y * 128;

    __shared__ float Ss[HDIM][HDIM];
    __shared__ float Qs[16][128];

    const int tid = threadIdx.x;

    {
        const float* Sb = g_S + (size_t)bh * HDIM * HDIM;
#pragma unroll
        for (int it = 0; it < 4; ++it) {
            int idx = tid + it * 256;
            int row = idx >> 4;
            int c4  = (idx & 15) * 4;
            *(float4*)&Ss[row][c4] = *(const float4*)(Sb + row * HDIM + c4);
        }
    }

    const int ty = tid >> 3;
    const int tx = tid & 7;

    float acc[4][8];
#pragma unroll
    for (int i = 0; i < 4; ++i)
#pragma unroll
        for (int j = 0; j < 8; ++j) acc[i][j] = 0.0f;

    const float* Qb = g_QKV + ((size_t)b * SEQ + m0) * NQKV + h * HDIM;

    for (int kb = 0; kb < 4; ++kb) {
        const int k0 = kb * 16;
#pragma unroll
        for (int it = 0; it < 2; ++it) {
            int idx = tid + it * 256;
            int row = idx >> 2;
            int kq  = (idx & 3) * 4;
            float4 v = *(const float4*)(Qb + (size_t)row * NQKV + k0 + kq);
            Qs[kq + 0][row] = v.x;
            Qs[kq + 1][row] = v.y;
            Qs[kq + 2][row] = v.z;
            Qs[kq + 3][row] = v.w;
        }
        __syncthreads();
#pragma unroll
        for (int kk = 0; kk < 16; ++kk) {
            float q[4], s[8];
#pragma unroll
            for (int i = 0; i < 4; ++i) q[i] = Qs[kk][ty * 4 + i];
            float4 s0 = *(const float4*)&Ss[k0 + kk][tx * 8];
            float4 s1 = *(const float4*)&Ss[k0 + kk][tx * 8 + 4];
            s[0]=s0.x; s[1]=s0.y; s[2]=s0.z; s[3]=s0.w;
            s[4]=s1.x; s[5]=s1.y; s[6]=s1.z; s[7]=s1.w;
#pragma unroll
            for (int i = 0; i < 4; ++i)
#pragma unroll
                for (int j = 0; j < 8; ++j)
                    acc[i][j] = fmaf(q[i], s[j], acc[i][j]);
        }
        __syncthreads();
    }

    // fused split epilogue: write fp16 hi/lo directly
#pragma unroll
    for (int i = 0; i < 4; ++i) {
        unsigned sh[8], sl[8];
#pragma unroll
        for (int j = 0; j < 8; ++j) {
            float f = acc[i][j];
            __half hb = __float2half_rn(f);
            float hf = __half2float(hb);
            __half lb = __float2half_rn(f - hf);
            sh[j] = (unsigned)__half_as_ushort(hb);
            sl[j] = (unsigned)__half_as_ushort(lb);
        }
        uint4 ph = make_uint4(sh[0] | (sh[1] << 16), sh[2] | (sh[3] << 16),
                              sh[4] | (sh[5] << 16), sh[6] | (sh[7] << 16));
        uint4 pl = make_uint4(sl[0] | (sl[1] << 16), sl[2] | (sl[3] << 16),
                              sl[4] | (sl[5] << 16), sl[6] | (sl[7] << 16));
        unsigned short* dst = (unsigned short*)g_ATTs +
            ((size_t)b * SEQ + m0 + ty * 4 + i) * KSP + h * HDIM + tx * 8;
        *(uint4*)dst          = ph;
        *(uint4*)(dst + HID)  = pl;   // lo block at column offset 1024
    }
}

// ---------------- launch ----------------------------------------------------
extern "C" void kernel_launch(void* const* d_in, const int* in_sizes, int n_in,
                              void* d_out, int out_size) {
    (void)in_sizes; (void)n_in; (void)out_size;
    const float* h   = (const float*)d_in[0];
    const float* Wq  = (const float*)d_in[1];
    const float* Wk  = (const float*)d_in[2];
    const float* Wv  = (const float*)d_in[3];
    // d_in[4] = Wspan (dead code in reference)
    const float* Wo  = (const float*)d_in[5];
    float* out = (float*)d_out;

    __half *pHs, *pWqkvh, *pWoh, *pATTs;
    float *pQKV, *pS;
    cudaGetSymbolAddress((void**)&pHs,    g_hs);
    cudaGetSymbolAddress((void**)&pWqkvh, g_Wqkvh);
    cudaGetSymbolAddress((void**)&pWoh,   g_Woh);
    cudaGetSymbolAddress((void**)&pATTs,  g_ATTs);
    cudaGetSymbolAddress((void**)&pQKV,   g_QKV);
    cudaGetSymbolAddress((void**)&pS,     g_S);

    cudaFuncSetAttribute(gemm_fp16,
                         cudaFuncAttributeMaxDynamicSharedMemorySize, GSMEM);

    // 1) h -> fp16 [hi|lo]; weights -> fp16 hi
    split16_kernel<<<ROWS, 256>>>(h, pHs, ROWS);
    cvt16_kernel<<<HID, 256>>>(Wq, pWqkvh,                       HID);
    cvt16_kernel<<<HID, 256>>>(Wk, pWqkvh + (size_t)HID * HID,   HID);
    cvt16_kernel<<<HID, 256>>>(Wv, pWqkvh + (size_t)2*HID*HID,   HID);
    cvt16_kernel<<<HID, 256>>>(Wo, pWoh, HID);

    // 2) fused QKV projection on tensor cores
    gemm_fp16<<<dim3(NQKV / 128, ROWS / 128), 256, GSMEM>>>(pHs, pWqkvh, pQKV, NQKV);

    // 3) attention via associativity: ATT = Q (K^T V), split fused into qs
    int nS = BATCH * NHEAD * HDIM * HDIM;
    zero_kernel<<<(nS + 255) / 256, 256>>>(pS, nS);
    ktv_kernel<<<dim3(BATCH * NHEAD, MSPLIT), 256>>>();
    qs_kernel<<<dim3(BATCH * NHEAD, SEQ / 128), 256>>>();

    // 4) output projection
    gemm_fp16<<<dim3(HID / 128, ROWS / 128), 256, GSMEM>>>(pATTs, pWoh, out, HID);
}

// round 6
// speedup vs baseline: 2.3550x; 1.6847x over previous
#include <cuda_runtime.h>
#include <cuda_fp16.h>
#include <cstdint>

// Problem constants
#define BATCH 2
#define SEQ   2048
#define HID   1024
#define NHEAD 16
#define HDIM  64
#define ROWS  (BATCH * SEQ)      // 4096
#define NQKV  3072               // fused QKV output width
#define NIT   32                 // 32 k-chunks of 32 (K = 1024, hi-only)

// ---------------- scratch (static device allocations; no cudaMalloc) --------
__device__ __half g_h16  [ROWS * HID];   // h fp16 (hi)
__device__ __half g_Wqkvh[NQKV * HID];   // [Wq;Wk;Wv] fp16 (hi)
__device__ __half g_Woh  [HID  * HID];   // Wo fp16 (hi)
__device__ __half g_ATTh [ROWS * HID];   // attention out fp16 (hi)
__device__ float g_QKV[ROWS * NQKV];     // fused projections (fp32)
__device__ float g_S  [BATCH * NHEAD * HDIM * HDIM];

// ---------------- helpers ----------------------------------------------------
__device__ __forceinline__ uint32_t smem_u32(const void* p) {
    uint32_t a;
    asm("{ .reg .u64 t; cvta.to.shared.u64 t, %1; cvt.u32.u64 %0, t; }"
        : "=r"(a) : "l"(p));
    return a;
}
__device__ __forceinline__ void cp16(uint32_t dst, const void* src) {
    asm volatile("cp.async.cg.shared.global [%0], [%1], 16;"
                 :: "r"(dst), "l"(src));
}

// ---- convert fp32 -> fp16, one row (1024 elems) per block -------------------
__global__ void cvt16_kernel(const float* __restrict__ X,
                             __half* __restrict__ Y) {
    size_t i = (size_t)blockIdx.x * 256 + threadIdx.x;
    float4 v = *(const float4*)(X + i * 4);
    unsigned s0 = __half_as_ushort(__float2half_rn(v.x));
    unsigned s1 = __half_as_ushort(__float2half_rn(v.y));
    unsigned s2 = __half_as_ushort(__float2half_rn(v.z));
    unsigned s3 = __half_as_ushort(__float2half_rn(v.w));
    *(uint2*)((unsigned short*)Y + i * 4) =
        make_uint2(s0 | (s1 << 16), s2 | (s3 << 16));
}

// ---- fused weight conversion: Wq,Wk,Wv -> g_Wqkvh; Wo -> g_Woh --------------
__global__ void cvtw_kernel(const float* __restrict__ Wq,
                            const float* __restrict__ Wk,
                            const float* __restrict__ Wv,
                            const float* __restrict__ Wo,
                            __half* __restrict__ Yqkv,
                            __half* __restrict__ Yo) {
    int blk = blockIdx.x;               // 0..4095, one row each
    int sel = blk >> 10;                // 0..3
    int row = blk & 1023;
    const float* src = (sel == 0) ? Wq : (sel == 1) ? Wk : (sel == 2) ? Wv : Wo;
    __half* dst = (sel == 3) ? (Yo + (size_t)row * HID)
                             : (Yqkv + ((size_t)sel * HID + row) * HID);
    int c4 = threadIdx.x * 4;
    float4 v = *(const float4*)(src + (size_t)row * HID + c4);
    unsigned s0 = __half_as_ushort(__float2half_rn(v.x));
    unsigned s1 = __half_as_ushort(__float2half_rn(v.y));
    unsigned s2 = __half_as_ushort(__float2half_rn(v.z));
    unsigned s3 = __half_as_ushort(__float2half_rn(v.w));
    *(uint2*)((unsigned short*)dst + c4) =
        make_uint2(s0 | (s1 << 16), s2 | (s3 << 16));
}

// ---------------- fp16 GEMM via mma.sync (m16n8k16), K = 1024 ---------------
// C[4096, N] fp32 = A[4096,1024] x B[N,1024]^T.
// Tile 128x128, 8 warps (2m x 4n), warp tile 64x32, 3-stage cp.async.
// Smem rows padded to 80B (64B data) -> conflict-free ldmatrix.
#define LDB    80                // smem row stride bytes
#define ASZ    10240             // 128*80 per tile
#define STAGE  20480             // A + B
#define GSMEM  (3 * STAGE)       // 61440
#define ROWB   2048              // gmem row stride bytes (1024 fp16)

__global__ __launch_bounds__(256, 2)
void gemm_fp16(const __half* __restrict__ A,
               const __half* __restrict__ B,
               float* __restrict__ C, int N) {
    extern __shared__ char sm[];
    const int tid = threadIdx.x, lane = tid & 31, wid = tid >> 5;
    const int wm = wid & 1, wn = wid >> 1;
    const int bm = blockIdx.y * 128, bn = blockIdx.x * 128;
    const uint32_t sb = smem_u32(sm);
    const char* Ag = (const char*)A + (size_t)bm * ROWB;
    const char* Bg = (const char*)B + (size_t)bn * ROWB;

    float acc[4][4][4];
#pragma unroll
    for (int mt = 0; mt < 4; ++mt)
#pragma unroll
        for (int nt = 0; nt < 4; ++nt)
#pragma unroll
            for (int j = 0; j < 4; ++j) acc[mt][nt][j] = 0.0f;

    const int lr = tid >> 2, lc = (tid & 3) * 16;

    auto load_stage = [&](int it) {
        int s = it % 3;
        int kb = (it & 31) * 64;         // byte offset of 32-col chunk
        uint32_t da = sb + s * STAGE, db = da + ASZ;
        const char* Ap = Ag + kb;
        const char* Bp = Bg + kb;
        cp16(da + lr * LDB + lc,        Ap + (size_t)lr * ROWB + lc);
        cp16(da + (lr + 64) * LDB + lc, Ap + (size_t)(lr + 64) * ROWB + lc);
        cp16(db + lr * LDB + lc,        Bp + (size_t)lr * ROWB + lc);
        cp16(db + (lr + 64) * LDB + lc, Bp + (size_t)(lr + 64) * ROWB + lc);
        asm volatile("cp.async.commit_group;" ::: "memory");
    };

    load_stage(0);
    load_stage(1);

    for (int it = 0; it < NIT; ++it) {
        if (it < NIT - 1) asm volatile("cp.async.wait_group 1;" ::: "memory");
        else              asm volatile("cp.async.wait_group 0;" ::: "memory");
        __syncthreads();
        if (it + 2 < NIT) load_stage(it + 2);

        int s = it % 3;
        uint32_t abase = sb + s * STAGE +
                         (wm * 64 + (lane & 15)) * LDB + ((lane >> 4) & 1) * 16;
        uint32_t bbase = sb + s * STAGE + ASZ +
                         (wn * 32 + (lane & 7) + ((lane >> 3) & 1) * 8) * LDB +
                         ((lane >> 4) & 1) * 16;
#pragma unroll
        for (int ks = 0; ks < 2; ++ks) {
            uint32_t a[4][4], b[4][2];
#pragma unroll
            for (int mt = 0; mt < 4; ++mt)
                asm volatile(
                    "ldmatrix.sync.aligned.m8n8.x4.shared.b16 {%0,%1,%2,%3}, [%4];"
                    : "=r"(a[mt][0]), "=r"(a[mt][1]), "=r"(a[mt][2]), "=r"(a[mt][3])
                    : "r"(abase + ks * 32 + mt * (16 * LDB)));
#pragma unroll
            for (int g = 0; g < 2; ++g)
                asm volatile(
                    "ldmatrix.sync.aligned.m8n8.x4.shared.b16 {%0,%1,%2,%3}, [%4];"
                    : "=r"(b[2 * g][0]), "=r"(b[2 * g + 1][0]),
                      "=r"(b[2 * g][1]), "=r"(b[2 * g + 1][1])
                    : "r"(bbase + ks * 32 + g * (16 * LDB)));
#pragma unroll
            for (int mt = 0; mt < 4; ++mt)
#pragma unroll
                for (int nt = 0; nt < 4; ++nt)
                    asm volatile(
                        "mma.sync.aligned.m16n8k16.row.col.f32.f16.f16.f32 "
                        "{%0,%1,%2,%3}, {%4,%5,%6,%7}, {%8,%9}, {%0,%1,%2,%3};"
                        : "+f"(acc[mt][nt][0]), "+f"(acc[mt][nt][1]),
                          "+f"(acc[mt][nt][2]), "+f"(acc[mt][nt][3])
                        : "r"(a[mt][0]), "r"(a[mt][1]), "r"(a[mt][2]), "r"(a[mt][3]),
                          "r"(b[nt][0]), "r"(b[nt][1]));
        }
    }

    // epilogue: direct float2 stores (C fragment layout)
#pragma unroll
    for (int mt = 0; mt < 4; ++mt)
#pragma unroll
        for (int nt = 0; nt < 4; ++nt) {
            int r0 = bm + wm * 64 + mt * 16 + (lane >> 2);
            int c0 = bn + wn * 32 + nt * 8 + (lane & 3) * 2;
            *(float2*)(C + (size_t)r0 * N + c0) =
                make_float2(acc[mt][nt][0], acc[mt][nt][1]);
            *(float2*)(C + (size_t)(r0 + 8) * N + c0) =
                make_float2(acc[mt][nt][2], acc[mt][nt][3]);
        }
}

// ---------------- zero S ----------------------------------------------------
__global__ void zero_kernel(float* __restrict__ p, int n) {
    int i = blockIdx.x * blockDim.x + threadIdx.x;
    if (i < n) p[i] = 0.0f;
}

// ---------------- S[b,h] = K_h^T @ V_h  (64x64, reduce over SEQ) ------------
#define MSPLIT 8
#define MCHUNK (SEQ / MSPLIT)   // 256

__global__ __launch_bounds__(256)
void ktv_kernel() {
    const int bh = blockIdx.x;
    const int b  = bh / NHEAD;
    const int h  = bh % NHEAD;
    const int mbase = blockIdx.y * MCHUNK;

    __shared__ float Ks[16][HDIM];
    __shared__ float Vs[16][HDIM];

    const int tid = threadIdx.x;
    const int t1 = (tid >> 4) * 4;
    const int t2 = (tid & 15) * 4;

    const float* Kb = g_QKV + ((size_t)b * SEQ) * NQKV + HID + h * HDIM;
    const float* Vb = g_QKV + ((size_t)b * SEQ) * NQKV + 2 * HID + h * HDIM;

    float acc[4][4];
#pragma unroll
    for (int i = 0; i < 4; ++i)
#pragma unroll
        for (int j = 0; j < 4; ++j) acc[i][j] = 0.0f;

    const int lrow = tid >> 4;
    const int lc4  = (tid & 15) * 4;

    for (int m0 = mbase; m0 < mbase + MCHUNK; m0 += 16) {
        float4 kv = *(const float4*)(Kb + (size_t)(m0 + lrow) * NQKV + lc4);
        float4 vv = *(const float4*)(Vb + (size_t)(m0 + lrow) * NQKV + lc4);
        *(float4*)&Ks[lrow][lc4] = kv;
        *(float4*)&Vs[lrow][lc4] = vv;
        __syncthreads();
#pragma unroll
        for (int m = 0; m < 16; ++m) {
            float a[4], v[4];
#pragma unroll
            for (int i = 0; i < 4; ++i) a[i] = Ks[m][t1 + i];
#pragma unroll
            for (int j = 0; j < 4; ++j) v[j] = Vs[m][t2 + j];
#pragma unroll
            for (int i = 0; i < 4; ++i)
#pragma unroll
                for (int j = 0; j < 4; ++j)
                    acc[i][j] = fmaf(a[i], v[j], acc[i][j]);
        }
        __syncthreads();
    }

    float* Sb = g_S + (size_t)bh * HDIM * HDIM;
#pragma unroll
    for (int i = 0; i < 4; ++i)
#pragma unroll
        for (int j = 0; j < 4; ++j)
            atomicAdd(&Sb[(t1 + i) * HDIM + t2 + j], acc[i][j]);
}

// -------- A[b,h] = Q_h @ S[b,h]  -> g_ATTh (fp16 hi epilogue) ---------------
__global__ __launch_bounds__(256)
void qs_kernel() {
    const int bh = blockIdx.x;
    const int b  = bh / NHEAD;
    const int h  = bh % NHEAD;
    const int m0 = blockIdx.y * 128;

    __shared__ float Ss[HDIM][HDIM];
    __shared__ float Qs[16][128];

    const int tid = threadIdx.x;

    {
        const float* Sb = g_S + (size_t)bh * HDIM * HDIM;
#pragma unroll
        for (int it = 0; it < 4; ++it) {
            int idx = tid + it * 256;
            int row = idx >> 4;
            int c4  = (idx & 15) * 4;
            *(float4*)&Ss[row][c4] = *(const float4*)(Sb + row * HDIM + c4);
        }
    }

    const int ty = tid >> 3;
    const int tx = tid & 7;

    float acc[4][8];
#pragma unroll
    for (int i = 0; i < 4; ++i)
#pragma unroll
        for (int j = 0; j < 8; ++j) acc[i][j] = 0.0f;

    const float* Qb = g_QKV + ((size_t)b * SEQ + m0) * NQKV + h * HDIM;

    for (int kb = 0; kb < 4; ++kb) {
        const int k0 = kb * 16;
#pragma unroll
        for (int it = 0; it < 2; ++it) {
            int idx = tid + it * 256;
            int row = idx >> 2;
            int kq  = (idx & 3) * 4;
            float4 v = *(const float4*)(Qb + (size_t)row * NQKV + k0 + kq);
            Qs[kq + 0][row] = v.x;
            Qs[kq + 1][row] = v.y;
            Qs[kq + 2][row] = v.z;
            Qs[kq + 3][row] = v.w;
        }
        __syncthreads();
#pragma unroll
        for (int kk = 0; kk < 16; ++kk) {
            float q[4], s[8];
#pragma unroll
            for (int i = 0; i < 4; ++i) q[i] = Qs[kk][ty * 4 + i];
            float4 s0 = *(const float4*)&Ss[k0 + kk][tx * 8];
            float4 s1 = *(const float4*)&Ss[k0 + kk][tx * 8 + 4];
            s[0]=s0.x; s[1]=s0.y; s[2]=s0.z; s[3]=s0.w;
            s[4]=s1.x; s[5]=s1.y; s[6]=s1.z; s[7]=s1.w;
#pragma unroll
            for (int i = 0; i < 4; ++i)
#pragma unroll
                for (int j = 0; j < 8; ++j)
                    acc[i][j] = fmaf(q[i], s[j], acc[i][j]);
        }
        __syncthreads();
    }

    // fp16 (hi) epilogue
#pragma unroll
    for (int i = 0; i < 4; ++i) {
        unsigned sh[8];
#pragma unroll
        for (int j = 0; j < 8; ++j)
            sh[j] = (unsigned)__half_as_ushort(__float2half_rn(acc[i][j]));
        uint4 ph = make_uint4(sh[0] | (sh[1] << 16), sh[2] | (sh[3] << 16),
                              sh[4] | (sh[5] << 16), sh[6] | (sh[7] << 16));
        unsigned short* dst = (unsigned short*)g_ATTh +
            ((size_t)b * SEQ + m0 + ty * 4 + i) * HID + h * HDIM + tx * 8;
        *(uint4*)dst = ph;
    }
}

// ---------------- launch ----------------------------------------------------
extern "C" void kernel_launch(void* const* d_in, const int* in_sizes, int n_in,
                              void* d_out, int out_size) {
    (void)in_sizes; (void)n_in; (void)out_size;
    const float* h   = (const float*)d_in[0];
    const float* Wq  = (const float*)d_in[1];
    const float* Wk  = (const float*)d_in[2];
    const float* Wv  = (const float*)d_in[3];
    // d_in[4] = Wspan (dead code in reference)
    const float* Wo  = (const float*)d_in[5];
    float* out = (float*)d_out;

    __half *pH16, *pWqkvh, *pWoh, *pATTh;
    float *pQKV, *pS;
    cudaGetSymbolAddress((void**)&pH16,   g_h16);
    cudaGetSymbolAddress((void**)&pWqkvh, g_Wqkvh);
    cudaGetSymbolAddress((void**)&pWoh,   g_Woh);
    cudaGetSymbolAddress((void**)&pATTh,  g_ATTh);
    cudaGetSymbolAddress((void**)&pQKV,   g_QKV);
    cudaGetSymbolAddress((void**)&pS,     g_S);

    cudaFuncSetAttribute(gemm_fp16,
                         cudaFuncAttributeMaxDynamicSharedMemorySize, GSMEM);

    // 1) fp32 -> fp16 conversions
    cvt16_kernel<<<ROWS, 256>>>(h, pH16);
    cvtw_kernel<<<4 * HID, 256>>>(Wq, Wk, Wv, Wo, pWqkvh, pWoh);

    // 2) fused QKV projection on tensor cores
    gemm_fp16<<<dim3(NQKV / 128, ROWS / 128), 256, GSMEM>>>(pH16, pWqkvh, pQKV, NQKV);

    // 3) attention via associativity: ATT = Q (K^T V)
    int nS = BATCH * NHEAD * HDIM * HDIM;
    zero_kernel<<<(nS + 255) / 256, 256>>>(pS, nS);
    ktv_kernel<<<dim3(BATCH * NHEAD, MSPLIT), 256>>>();
    qs_kernel<<<dim3(BATCH * NHEAD, SEQ / 128), 256>>>();

    // 4) output projection
    gemm_fp16<<<dim3(HID / 128, ROWS / 128), 256, GSMEM>>>(pATTh, pWoh, out, HID);
}

// round 7
// speedup vs baseline: 2.4245x; 1.0295x over previous
#include <cuda_runtime.h>
#include <cuda_fp16.h>
#include <cstdint>

// Problem constants
#define BATCH 2
#define SEQ   2048
#define HID   1024
#define NHEAD 16
#define HDIM  64
#define ROWS  (BATCH * SEQ)      // 4096
#define NQKV  3072               // fused QKV output width
#define NIT   32                 // 32 k-chunks of 32 (K = 1024)

// ---------------- scratch (static device allocations; no cudaMalloc) --------
__device__ __half g_h16  [ROWS * HID];     // h fp16
__device__ __half g_Wqkvh[NQKV * HID];     // [Wq;Wk;Wv] fp16
__device__ __half g_Qh   [ROWS * HID];     // Q projection, fp16 (GEMM1 epilogue)
__device__ float  g_KV   [ROWS * 2048];    // [K | V] projections, fp32
__device__ __half g_U    [BATCH * HID * HID]; // U_b in B-layout: [j, h*64+e]
__device__ float  g_S    [BATCH * NHEAD * HDIM * HDIM];

// ---------------- helpers ----------------------------------------------------
__device__ __forceinline__ uint32_t smem_u32(const void* p) {
    uint32_t a;
    asm("{ .reg .u64 t; cvta.to.shared.u64 t, %1; cvt.u32.u64 %0, t; }"
        : "=r"(a) : "l"(p));
    return a;
}
__device__ __forceinline__ void cp16(uint32_t dst, const void* src) {
    asm volatile("cp.async.cg.shared.global [%0], [%1], 16;"
                 :: "r"(dst), "l"(src));
}

// ---- convert fp32 -> fp16 (1024 elems per block row) ------------------------
__global__ void cvt16_kernel(const float* __restrict__ X,
                             __half* __restrict__ Y) {
    size_t i = (size_t)blockIdx.x * 256 + threadIdx.x;
    float4 v = *(const float4*)(X + i * 4);
    unsigned s0 = __half_as_ushort(__float2half_rn(v.x));
    unsigned s1 = __half_as_ushort(__float2half_rn(v.y));
    unsigned s2 = __half_as_ushort(__float2half_rn(v.z));
    unsigned s3 = __half_as_ushort(__float2half_rn(v.w));
    *(uint2*)((unsigned short*)Y + i * 4) =
        make_uint2(s0 | (s1 << 16), s2 | (s3 << 16));
}

// ---- fused weight conversion: Wq,Wk,Wv -> g_Wqkvh ---------------------------
__global__ void cvtw_kernel(const float* __restrict__ Wq,
                            const float* __restrict__ Wk,
                            const float* __restrict__ Wv,
                            __half* __restrict__ Yqkv) {
    int blk = blockIdx.x;               // 0..3071, one row each
    int sel = blk >> 10;                // 0..2
    int row = blk & 1023;
    const float* src = (sel == 0) ? Wq : (sel == 1) ? Wk : Wv;
    __half* dst = Yqkv + ((size_t)sel * HID + row) * HID;
    int c4 = threadIdx.x * 4;
    float4 v = *(const float4*)(src + (size_t)row * HID + c4);
    unsigned s0 = __half_as_ushort(__float2half_rn(v.x));
    unsigned s1 = __half_as_ushort(__float2half_rn(v.y));
    unsigned s2 = __half_as_ushort(__float2half_rn(v.z));
    unsigned s3 = __half_as_ushort(__float2half_rn(v.w));
    *(uint2*)((unsigned short*)dst + c4) =
        make_uint2(s0 | (s1 << 16), s2 | (s3 << 16));
}

// ---------------- fp16 GEMM via mma.sync (m16n8k16), K = 1024 ---------------
// C = A[Mx1024] x B[Nx1024]^T. Tile 128x128, 8 warps, 3-stage cp.async.
// Epilogue: tiles with bn < qcols -> fp16 into Ch (ld 1024);
//           else fp32 into Cf at col (bn - qcols), leading dim ldc.
// B pointer advanced by bstride elements per 2048-row batch (for per-batch U).
#define LDB    80
#define ASZ    10240
#define STAGE  20480
#define GSMEM  (3 * STAGE)       // 61440
#define ROWB   2048              // gmem row stride bytes (1024 fp16)

__global__ __launch_bounds__(256, 2)
void gemm_fp16(const __half* __restrict__ A,
               const __half* __restrict__ B,
               float* __restrict__ Cf, int ldc,
               __half* __restrict__ Ch, int qcols, size_t bstride) {
    extern __shared__ char sm[];
    const int tid = threadIdx.x, lane = tid & 31, wid = tid >> 5;
    const int wm = wid & 1, wn = wid >> 1;
    const int bm = blockIdx.y * 128, bn = blockIdx.x * 128;
    const uint32_t sb = smem_u32(sm);
    const char* Ag = (const char*)A + (size_t)bm * ROWB;
    const char* Bg = (const char*)(B + (size_t)(bm >> 11) * bstride) +
                     (size_t)bn * ROWB;

    float acc[4][4][4];
#pragma unroll
    for (int mt = 0; mt < 4; ++mt)
#pragma unroll
        for (int nt = 0; nt < 4; ++nt)
#pragma unroll
            for (int j = 0; j < 4; ++j) acc[mt][nt][j] = 0.0f;

    const int lr = tid >> 2, lc = (tid & 3) * 16;

    auto load_stage = [&](int it) {
        int s = it % 3;
        int kb = (it & 31) * 64;
        uint32_t da = sb + s * STAGE, db = da + ASZ;
        const char* Ap = Ag + kb;
        const char* Bp = Bg + kb;
        cp16(da + lr * LDB + lc,        Ap + (size_t)lr * ROWB + lc);
        cp16(da + (lr + 64) * LDB + lc, Ap + (size_t)(lr + 64) * ROWB + lc);
        cp16(db + lr * LDB + lc,        Bp + (size_t)lr * ROWB + lc);
        cp16(db + (lr + 64) * LDB + lc, Bp + (size_t)(lr + 64) * ROWB + lc);
        asm volatile("cp.async.commit_group;" ::: "memory");
    };

    load_stage(0);
    load_stage(1);

    for (int it = 0; it < NIT; ++it) {
        if (it < NIT - 1) asm volatile("cp.async.wait_group 1;" ::: "memory");
        else              asm volatile("cp.async.wait_group 0;" ::: "memory");
        __syncthreads();
        if (it + 2 < NIT) load_stage(it + 2);

        int s = it % 3;
        uint32_t abase = sb + s * STAGE +
                         (wm * 64 + (lane & 15)) * LDB + ((lane >> 4) & 1) * 16;
        uint32_t bbase = sb + s * STAGE + ASZ +
                         (wn * 32 + (lane & 7) + ((lane >> 3) & 1) * 8) * LDB +
                         ((lane >> 4) & 1) * 16;
#pragma unroll
        for (int ks = 0; ks < 2; ++ks) {
            uint32_t a[4][4], b[4][2];
#pragma unroll
            for (int mt = 0; mt < 4; ++mt)
                asm volatile(
                    "ldmatrix.sync.aligned.m8n8.x4.shared.b16 {%0,%1,%2,%3}, [%4];"
                    : "=r"(a[mt][0]), "=r"(a[mt][1]), "=r"(a[mt][2]), "=r"(a[mt][3])
                    : "r"(abase + ks * 32 + mt * (16 * LDB)));
#pragma unroll
            for (int g = 0; g < 2; ++g)
                asm volatile(
                    "ldmatrix.sync.aligned.m8n8.x4.shared.b16 {%0,%1,%2,%3}, [%4];"
                    : "=r"(b[2 * g][0]), "=r"(b[2 * g + 1][0]),
                      "=r"(b[2 * g][1]), "=r"(b[2 * g + 1][1])
                    : "r"(bbase + ks * 32 + g * (16 * LDB)));
#pragma unroll
            for (int mt = 0; mt < 4; ++mt)
#pragma unroll
                for (int nt = 0; nt < 4; ++nt)
                    asm volatile(
                        "mma.sync.aligned.m16n8k16.row.col.f32.f16.f16.f32 "
                        "{%0,%1,%2,%3}, {%4,%5,%6,%7}, {%8,%9}, {%0,%1,%2,%3};"
                        : "+f"(acc[mt][nt][0]), "+f"(acc[mt][nt][1]),
                          "+f"(acc[mt][nt][2]), "+f"(acc[mt][nt][3])
                        : "r"(a[mt][0]), "r"(a[mt][1]), "r"(a[mt][2]), "r"(a[mt][3]),
                          "r"(b[nt][0]), "r"(b[nt][1]));
        }
    }

    if (bn < qcols) {
        // fp16 epilogue (Q tiles)
#pragma unroll
        for (int mt = 0; mt < 4; ++mt)
#pragma unroll
            for (int nt = 0; nt < 4; ++nt) {
                int r0 = bm + wm * 64 + mt * 16 + (lane >> 2);
                int c0 = bn + wn * 32 + nt * 8 + (lane & 3) * 2;
                *(__half2*)(Ch + (size_t)r0 * HID + c0) =
                    __floats2half2_rn(acc[mt][nt][0], acc[mt][nt][1]);
                *(__half2*)(Ch + (size_t)(r0 + 8) * HID + c0) =
                    __floats2half2_rn(acc[mt][nt][2], acc[mt][nt][3]);
            }
    } else {
        int cb = bn - qcols;
#pragma unroll
        for (int mt = 0; mt < 4; ++mt)
#pragma unroll
            for (int nt = 0; nt < 4; ++nt) {
                int r0 = bm + wm * 64 + mt * 16 + (lane >> 2);
                int c0 = cb + wn * 32 + nt * 8 + (lane & 3) * 2;
                *(float2*)(Cf + (size_t)r0 * ldc + c0) =
                    make_float2(acc[mt][nt][0], acc[mt][nt][1]);
                *(float2*)(Cf + (size_t)(r0 + 8) * ldc + c0) =
                    make_float2(acc[mt][nt][2], acc[mt][nt][3]);
            }
    }
}

// ---------------- S[b,h] = K_h^T @ V_h  (64x64, reduce over SEQ) ------------
#define MSPLIT 8
#define MCHUNK (SEQ / MSPLIT)   // 256
#define KVLD   2048             // g_KV row stride (floats)

__global__ __launch_bounds__(256)
void ktv_kernel() {
    const int bh = blockIdx.x;
    const int b  = bh / NHEAD;
    const int h  = bh % NHEAD;
    const int mbase = blockIdx.y * MCHUNK;

    __shared__ float Ks[16][HDIM];
    __shared__ float Vs[16][HDIM];

    const int tid = threadIdx.x;
    const int t1 = (tid >> 4) * 4;
    const int t2 = (tid & 15) * 4;

    const float* Kb = g_KV + ((size_t)b * SEQ) * KVLD + h * HDIM;
    const float* Vb = g_KV + ((size_t)b * SEQ) * KVLD + 1024 + h * HDIM;

    float acc[4][4];
#pragma unroll
    for (int i = 0; i < 4; ++i)
#pragma unroll
        for (int j = 0; j < 4; ++j) acc[i][j] = 0.0f;

    const int lrow = tid >> 4;
    const int lc4  = (tid & 15) * 4;

    for (int m0 = mbase; m0 < mbase + MCHUNK; m0 += 16) {
        float4 kv = *(const float4*)(Kb + (size_t)(m0 + lrow) * KVLD + lc4);
        float4 vv = *(const float4*)(Vb + (size_t)(m0 + lrow) * KVLD + lc4);
        *(float4*)&Ks[lrow][lc4] = kv;
        *(float4*)&Vs[lrow][lc4] = vv;
        __syncthreads();
#pragma unroll
        for (int m = 0; m < 16; ++m) {
            float a[4], v[4];
#pragma unroll
            for (int i = 0; i < 4; ++i) a[i] = Ks[m][t1 + i];
#pragma unroll
            for (int j = 0; j < 4; ++j) v[j] = Vs[m][t2 + j];
#pragma unroll
            for (int i = 0; i < 4; ++i)
#pragma unroll
                for (int j = 0; j < 4; ++j)
                    acc[i][j] = fmaf(a[i], v[j], acc[i][j]);
        }
        __syncthreads();
    }

    float* Sb = g_S + (size_t)bh * HDIM * HDIM;
#pragma unroll
    for (int i = 0; i < 4; ++i)
#pragma unroll
        for (int j = 0; j < 4; ++j)
            atomicAdd(&Sb[(t1 + i) * HDIM + t2 + j], acc[i][j]);
}

// ---- U_b in B-layout: g_U[b][j*1024 + h*64+e] = sum_d S_h[e,d]*Wo[j,h*64+d] -
// grid (BATCH*NHEAD, 8 j-chunks of 128); 256 threads.
__global__ __launch_bounds__(256)
void u_kernel(const float* __restrict__ Wo) {
    const int bh = blockIdx.x;
    const int b  = bh / NHEAD;
    const int h  = bh % NHEAD;
    const int jbase = blockIdx.y * 128;

    __shared__ float Ss[HDIM][HDIM + 1];
    const int tid = threadIdx.x;
    {
        const float* Sb = g_S + (size_t)bh * HDIM * HDIM;
#pragma unroll
        for (int it = 0; it < 4; ++it) {
            int idx = tid + it * 256;           // float4 index
            int row = idx >> 4;
            int c4  = (idx & 15) * 4;
            float4 v = *(const float4*)(Sb + row * HDIM + c4);
            Ss[row][c4 + 0] = v.x; Ss[row][c4 + 1] = v.y;
            Ss[row][c4 + 2] = v.z; Ss[row][c4 + 3] = v.w;
        }
    }
    __syncthreads();

    const int jloc = tid >> 1;
    const int eh = (tid & 1) * 32;
    const int j = jbase + jloc;
    const float* wrow = Wo + (size_t)j * HID + h * HDIM;

    float acc[32];
#pragma unroll
    for (int e = 0; e < 32; ++e) acc[e] = 0.0f;

#pragma unroll
    for (int d4 = 0; d4 < HDIM; d4 += 4) {
        float4 w = *(const float4*)(wrow + d4);
#pragma unroll
        for (int e = 0; e < 32; ++e) {
            float s = fmaf(w.x, Ss[eh + e][d4 + 0],
                      fmaf(w.y, Ss[eh + e][d4 + 1],
                      fmaf(w.z, Ss[eh + e][d4 + 2],
                           w.w * Ss[eh + e][d4 + 3])));
            acc[e] += s;
        }
    }

    unsigned short* dst = (unsigned short*)g_U +
        ((size_t)b * HID + j) * HID + h * HDIM + eh;
#pragma unroll
    for (int q = 0; q < 4; ++q) {
        unsigned p[4];
#pragma unroll
        for (int t = 0; t < 4; ++t) {
            unsigned lo2 = __half_as_ushort(__float2half_rn(acc[q * 8 + t * 2]));
            unsigned hi2 = __half_as_ushort(__float2half_rn(acc[q * 8 + t * 2 + 1]));
            p[t] = lo2 | (hi2 << 16);
        }
        *(uint4*)(dst + q * 8) = make_uint4(p[0], p[1], p[2], p[3]);
    }
}

// ---------------- launch ----------------------------------------------------
extern "C" void kernel_launch(void* const* d_in, const int* in_sizes, int n_in,
                              void* d_out, int out_size) {
    (void)in_sizes; (void)n_in; (void)out_size;
    const float* h   = (const float*)d_in[0];
    const float* Wq  = (const float*)d_in[1];
    const float* Wk  = (const float*)d_in[2];
    const float* Wv  = (const float*)d_in[3];
    // d_in[4] = Wspan (dead code in reference)
    const float* Wo  = (const float*)d_in[5];
    float* out = (float*)d_out;

    __half *pH16, *pWqkvh, *pQh, *pU;
    float *pKV, *pS;
    cudaGetSymbolAddress((void**)&pH16,   g_h16);
    cudaGetSymbolAddress((void**)&pWqkvh, g_Wqkvh);
    cudaGetSymbolAddress((void**)&pQh,    g_Qh);
    cudaGetSymbolAddress((void**)&pU,     g_U);
    cudaGetSymbolAddress((void**)&pKV,    g_KV);
    cudaGetSymbolAddress((void**)&pS,     g_S);

    cudaFuncSetAttribute(gemm_fp16,
                         cudaFuncAttributeMaxDynamicSharedMemorySize, GSMEM);

    // 1) fp32 -> fp16 conversions
    cvt16_kernel<<<ROWS, 256>>>(h, pH16);
    cvtw_kernel<<<3 * HID, 256>>>(Wq, Wk, Wv, pWqkvh);

    // 2) fused QKV projection: Q -> fp16 g_Qh; K,V -> fp32 g_KV
    gemm_fp16<<<dim3(NQKV / 128, ROWS / 128), 256, GSMEM>>>(
        pH16, pWqkvh, pKV, 2048, pQh, 1024, 0);

    // 3) S = K^T V per (b,h); then U_b = S_h * Wo_h^T folded into B-layout
    cudaMemsetAsync(pS, 0, (size_t)BATCH * NHEAD * HDIM * HDIM * sizeof(float));
    ktv_kernel<<<dim3(BATCH * NHEAD, MSPLIT), 256>>>();
    u_kernel<<<dim3(BATCH * NHEAD, 8), 256>>>(Wo);

    // 4) out = Q_cat @ U_b  (per-batch B via bstride)
    gemm_fp16<<<dim3(HID / 128, ROWS / 128), 256, GSMEM>>>(
        pQh, pU, out, 1024, nullptr, 0, (size_t)HID * HID);
}

// round 8
// speedup vs baseline: 2.5298x; 1.0434x over previous
#include <cuda_runtime.h>
#include <cuda_fp16.h>
#include <cstdint>

// Problem constants
#define BATCH 2
#define SEQ   2048
#define HID   1024
#define NHEAD 16
#define HDIM  64
#define ROWS  (BATCH * SEQ)      // 4096
#define NIT   32                 // 32 k-chunks of 32 (K = 1024)

// ---------------- scratch (static device allocations; no cudaMalloc) --------
__device__ __half g_h16 [ROWS * HID];       // h fp16 (A for GEMM1 and GEMM2)
__device__ __half g_Wkvh[2048 * HID];       // [Wk;Wv] fp16 (B layout)
__device__ __half g_WqT [HID * HID];        // Wq^T fp16: [c][t] = Wq[t][c]
__device__ float  g_KV  [ROWS * 2048];      // [K | V] projections, fp32
__device__ __half g_U   [BATCH * HID * HID];// g_U[b*1024+j][t] = U_b[t,j]
__device__ __half g_W2  [BATCH * HID * HID];// W2_b[j][c] (B layout for GEMM2)
__device__ float  g_S   [BATCH * NHEAD * HDIM * HDIM];

// ---------------- helpers ----------------------------------------------------
__device__ __forceinline__ uint32_t smem_u32(const void* p) {
    uint32_t a;
    asm("{ .reg .u64 t; cvta.to.shared.u64 t, %1; cvt.u32.u64 %0, t; }"
        : "=r"(a) : "l"(p));
    return a;
}
__device__ __forceinline__ void cp16(uint32_t dst, const void* src) {
    asm volatile("cp.async.cg.shared.global [%0], [%1], 16;"
                 :: "r"(dst), "l"(src));
}

// ---- convert fp32 -> fp16 (flat) --------------------------------------------
__global__ void cvt16_kernel(const float* __restrict__ X,
                             __half* __restrict__ Y) {
    size_t i = (size_t)blockIdx.x * 256 + threadIdx.x;
    float4 v = *(const float4*)(X + i * 4);
    unsigned s0 = __half_as_ushort(__float2half_rn(v.x));
    unsigned s1 = __half_as_ushort(__float2half_rn(v.y));
    unsigned s2 = __half_as_ushort(__float2half_rn(v.z));
    unsigned s3 = __half_as_ushort(__float2half_rn(v.w));
    *(uint2*)((unsigned short*)Y + i * 4) =
        make_uint2(s0 | (s1 << 16), s2 | (s3 << 16));
}

// ---- fused: Wk,Wv -> g_Wkvh -------------------------------------------------
__global__ void cvtw_kernel(const float* __restrict__ Wk,
                            const float* __restrict__ Wv,
                            __half* __restrict__ Y) {
    int blk = blockIdx.x;               // 0..2047, one row each
    int sel = blk >> 10;                // 0..1
    int row = blk & 1023;
    const float* src = (sel == 0) ? Wk : Wv;
    __half* dst = Y + ((size_t)sel * HID + row) * HID;
    int c4 = threadIdx.x * 4;
    float4 v = *(const float4*)(src + (size_t)row * HID + c4);
    unsigned s0 = __half_as_ushort(__float2half_rn(v.x));
    unsigned s1 = __half_as_ushort(__float2half_rn(v.y));
    unsigned s2 = __half_as_ushort(__float2half_rn(v.z));
    unsigned s3 = __half_as_ushort(__float2half_rn(v.w));
    *(uint2*)((unsigned short*)dst + c4) =
        make_uint2(s0 | (s1 << 16), s2 | (s3 << 16));
}

// ---- transpose + convert: WqT[c][t] = fp16(Wq[t][c]) ------------------------
__global__ void cvtwqT_kernel(const float* __restrict__ Wq,
                              __half* __restrict__ WqT) {
    __shared__ float tile[32][33];
    int bx = blockIdx.x * 32, by = blockIdx.y * 32;
    int tx = threadIdx.x, ty = threadIdx.y;   // (32, 8)
#pragma unroll
    for (int i = 0; i < 32; i += 8)
        tile[ty + i][tx] = Wq[(size_t)(by + ty + i) * HID + bx + tx];
    __syncthreads();
#pragma unroll
    for (int i = 0; i < 32; i += 8)
        WqT[(size_t)(bx + ty + i) * HID + by + tx] =
            __float2half_rn(tile[tx][ty + i]);
}

// ---------------- fp16 GEMM via mma.sync (m16n8k16), K = 1024 ---------------
// C = A[Mx1024] x B[Nx1024]^T. Tile 128x128, 8 warps, 3-stage cp.async.
// fp16out != 0 -> fp16 epilogue into Ch (ld 1024); else fp32 into Cf (ld ldc).
// B pointer advanced by bstride elements per 2048-row batch.
#define LDB    80
#define ASZ    10240
#define STAGE  20480
#define GSMEM  (3 * STAGE)       // 61440
#define ROWB   2048              // gmem row stride bytes (1024 fp16)

__global__ __launch_bounds__(256, 2)
void gemm_fp16(const __half* __restrict__ A,
               const __half* __restrict__ B,
               float* __restrict__ Cf, int ldc,
               __half* __restrict__ Ch, int fp16out, size_t bstride) {
    extern __shared__ char sm[];
    const int tid = threadIdx.x, lane = tid & 31, wid = tid >> 5;
    const int wm = wid & 1, wn = wid >> 1;
    const int bm = blockIdx.y * 128, bn = blockIdx.x * 128;
    const uint32_t sb = smem_u32(sm);
    const char* Ag = (const char*)A + (size_t)bm * ROWB;
    const char* Bg = (const char*)(B + (size_t)(bm >> 11) * bstride) +
                     (size_t)bn * ROWB;

    float acc[4][4][4];
#pragma unroll
    for (int mt = 0; mt < 4; ++mt)
#pragma unroll
        for (int nt = 0; nt < 4; ++nt)
#pragma unroll
            for (int j = 0; j < 4; ++j) acc[mt][nt][j] = 0.0f;

    const int lr = tid >> 2, lc = (tid & 3) * 16;

    auto load_stage = [&](int it) {
        int s = it % 3;
        int kb = (it & 31) * 64;
        uint32_t da = sb + s * STAGE, db = da + ASZ;
        const char* Ap = Ag + kb;
        const char* Bp = Bg + kb;
        cp16(da + lr * LDB + lc,        Ap + (size_t)lr * ROWB + lc);
        cp16(da + (lr + 64) * LDB + lc, Ap + (size_t)(lr + 64) * ROWB + lc);
        cp16(db + lr * LDB + lc,        Bp + (size_t)lr * ROWB + lc);
        cp16(db + (lr + 64) * LDB + lc, Bp + (size_t)(lr + 64) * ROWB + lc);
        asm volatile("cp.async.commit_group;" ::: "memory");
    };

    load_stage(0);
    load_stage(1);

    for (int it = 0; it < NIT; ++it) {
        if (it < NIT - 1) asm volatile("cp.async.wait_group 1;" ::: "memory");
        else              asm volatile("cp.async.wait_group 0;" ::: "memory");
        __syncthreads();
        if (it + 2 < NIT) load_stage(it + 2);

        int s = it % 3;
        uint32_t abase = sb + s * STAGE +
                         (wm * 64 + (lane & 15)) * LDB + ((lane >> 4) & 1) * 16;
        uint32_t bbase = sb + s * STAGE + ASZ +
                         (wn * 32 + (lane & 7) + ((lane >> 3) & 1) * 8) * LDB +
                         ((lane >> 4) & 1) * 16;
#pragma unroll
        for (int ks = 0; ks < 2; ++ks) {
            uint32_t a[4][4], b[4][2];
#pragma unroll
            for (int mt = 0; mt < 4; ++mt)
                asm volatile(
                    "ldmatrix.sync.aligned.m8n8.x4.shared.b16 {%0,%1,%2,%3}, [%4];"
                    : "=r"(a[mt][0]), "=r"(a[mt][1]), "=r"(a[mt][2]), "=r"(a[mt][3])
                    : "r"(abase + ks * 32 + mt * (16 * LDB)));
#pragma unroll
            for (int g = 0; g < 2; ++g)
                asm volatile(
                    "ldmatrix.sync.aligned.m8n8.x4.shared.b16 {%0,%1,%2,%3}, [%4];"
                    : "=r"(b[2 * g][0]), "=r"(b[2 * g + 1][0]),
                      "=r"(b[2 * g][1]), "=r"(b[2 * g + 1][1])
                    : "r"(bbase + ks * 32 + g * (16 * LDB)));
#pragma unroll
            for (int mt = 0; mt < 4; ++mt)
#pragma unroll
                for (int nt = 0; nt < 4; ++nt)
                    asm volatile(
                        "mma.sync.aligned.m16n8k16.row.col.f32.f16.f16.f32 "
                        "{%0,%1,%2,%3}, {%4,%5,%6,%7}, {%8,%9}, {%0,%1,%2,%3};"
                        : "+f"(acc[mt][nt][0]), "+f"(acc[mt][nt][1]),
                          "+f"(acc[mt][nt][2]), "+f"(acc[mt][nt][3])
                        : "r"(a[mt][0]), "r"(a[mt][1]), "r"(a[mt][2]), "r"(a[mt][3]),
                          "r"(b[nt][0]), "r"(b[nt][1]));
        }
    }

    if (fp16out) {
#pragma unroll
        for (int mt = 0; mt < 4; ++mt)
#pragma unroll
            for (int nt = 0; nt < 4; ++nt) {
                int r0 = bm + wm * 64 + mt * 16 + (lane >> 2);
                int c0 = bn + wn * 32 + nt * 8 + (lane & 3) * 2;
                *(__half2*)(Ch + (size_t)r0 * HID + c0) =
                    __floats2half2_rn(acc[mt][nt][0], acc[mt][nt][1]);
                *(__half2*)(Ch + (size_t)(r0 + 8) * HID + c0) =
                    __floats2half2_rn(acc[mt][nt][2], acc[mt][nt][3]);
            }
    } else {
#pragma unroll
        for (int mt = 0; mt < 4; ++mt)
#pragma unroll
            for (int nt = 0; nt < 4; ++nt) {
                int r0 = bm + wm * 64 + mt * 16 + (lane >> 2);
                int c0 = bn + wn * 32 + nt * 8 + (lane & 3) * 2;
                *(float2*)(Cf + (size_t)r0 * ldc + c0) =
                    make_float2(acc[mt][nt][0], acc[mt][nt][1]);
                *(float2*)(Cf + (size_t)(r0 + 8) * ldc + c0) =
                    make_float2(acc[mt][nt][2], acc[mt][nt][3]);
            }
    }
}

// ---------------- S[b,h] = K_h^T @ V_h  (64x64, reduce over SEQ) ------------
#define MSPLIT 32
#define MCHUNK (SEQ / MSPLIT)   // 64
#define KVLD   2048             // g_KV row stride (floats)

__global__ __launch_bounds__(256)
void ktv_kernel() {
    const int bh = blockIdx.x;
    const int b  = bh / NHEAD;
    const int h  = bh % NHEAD;
    const int mbase = blockIdx.y * MCHUNK;

    __shared__ float Ks[16][HDIM];
    __shared__ float Vs[16][HDIM];

    const int tid = threadIdx.x;
    const int t1 = (tid >> 4) * 4;
    const int t2 = (tid & 15) * 4;

    const float* Kb = g_KV + ((size_t)b * SEQ) * KVLD + h * HDIM;
    const float* Vb = g_KV + ((size_t)b * SEQ) * KVLD + 1024 + h * HDIM;

    float acc[4][4];
#pragma unroll
    for (int i = 0; i < 4; ++i)
#pragma unroll
        for (int j = 0; j < 4; ++j) acc[i][j] = 0.0f;

    const int lrow = tid >> 4;
    const int lc4  = (tid & 15) * 4;

#pragma unroll
    for (int mc = 0; mc < MCHUNK / 16; ++mc) {
        int m0 = mbase + mc * 16;
        float4 kv = *(const float4*)(Kb + (size_t)(m0 + lrow) * KVLD + lc4);
        float4 vv = *(const float4*)(Vb + (size_t)(m0 + lrow) * KVLD + lc4);
        *(float4*)&Ks[lrow][lc4] = kv;
        *(float4*)&Vs[lrow][lc4] = vv;
        __syncthreads();
#pragma unroll
        for (int m = 0; m < 16; ++m) {
            float a[4], v[4];
#pragma unroll
            for (int i = 0; i < 4; ++i) a[i] = Ks[m][t1 + i];
#pragma unroll
            for (int j = 0; j < 4; ++j) v[j] = Vs[m][t2 + j];
#pragma unroll
            for (int i = 0; i < 4; ++i)
#pragma unroll
                for (int j = 0; j < 4; ++j)
                    acc[i][j] = fmaf(a[i], v[j], acc[i][j]);
        }
        __syncthreads();
    }

    float* Sb = g_S + (size_t)bh * HDIM * HDIM;
#pragma unroll
    for (int i = 0; i < 4; ++i)
#pragma unroll
        for (int j = 0; j < 4; ++j)
            atomicAdd(&Sb[(t1 + i) * HDIM + t2 + j], acc[i][j]);
}

// ---- g_U[b*1024+j][h*64+e] = sum_d S_h[e,d]*Wo[j,h*64+d]  (fp16) -----------
__global__ __launch_bounds__(256)
void u_kernel(const float* __restrict__ Wo) {
    const int bh = blockIdx.x;
    const int b  = bh / NHEAD;
    const int h  = bh % NHEAD;
    const int jbase = blockIdx.y * 128;

    __shared__ float Ss[HDIM][HDIM + 1];
    const int tid = threadIdx.x;
    {
        const float* Sb = g_S + (size_t)bh * HDIM * HDIM;
#pragma unroll
        for (int it = 0; it < 4; ++it) {
            int idx = tid + it * 256;
            int row = idx >> 4;
            int c4  = (idx & 15) * 4;
            float4 v = *(const float4*)(Sb + row * HDIM + c4);
            Ss[row][c4 + 0] = v.x; Ss[row][c4 + 1] = v.y;
            Ss[row][c4 + 2] = v.z; Ss[row][c4 + 3] = v.w;
        }
    }
    __syncthreads();

    const int jloc = tid >> 1;
    const int eh = (tid & 1) * 32;
    const int j = jbase + jloc;
    const float* wrow = Wo + (size_t)j * HID + h * HDIM;

    float acc[32];
#pragma unroll
    for (int e = 0; e < 32; ++e) acc[e] = 0.0f;

#pragma unroll
    for (int d4 = 0; d4 < HDIM; d4 += 4) {
        float4 w = *(const float4*)(wrow + d4);
#pragma unroll
        for (int e = 0; e < 32; ++e) {
            float s = fmaf(w.x, Ss[eh + e][d4 + 0],
                      fmaf(w.y, Ss[eh + e][d4 + 1],
                      fmaf(w.z, Ss[eh + e][d4 + 2],
                           w.w * Ss[eh + e][d4 + 3])));
            acc[e] += s;
        }
    }

    unsigned short* dst = (unsigned short*)g_U +
        ((size_t)b * HID + j) * HID + h * HDIM + eh;
#pragma unroll
    for (int q = 0; q < 4; ++q) {
        unsigned p[4];
#pragma unroll
        for (int t = 0; t < 4; ++t) {
            unsigned lo2 = __half_as_ushort(__float2half_rn(acc[q * 8 + t * 2]));
            unsigned hi2 = __half_as_ushort(__float2half_rn(acc[q * 8 + t * 2 + 1]));
            p[t] = lo2 | (hi2 << 16);
        }
        *(uint4*)(dst + q * 8) = make_uint4(p[0], p[1], p[2], p[3]);
    }
}

// ---------------- launch ----------------------------------------------------
extern "C" void kernel_launch(void* const* d_in, const int* in_sizes, int n_in,
                              void* d_out, int out_size) {
    (void)in_sizes; (void)n_in; (void)out_size;
    const float* h   = (const float*)d_in[0];
    const float* Wq  = (const float*)d_in[1];
    const float* Wk  = (const float*)d_in[2];
    const float* Wv  = (const float*)d_in[3];
    // d_in[4] = Wspan (dead code in reference)
    const float* Wo  = (const float*)d_in[5];
    float* out = (float*)d_out;

    __half *pH16, *pWkvh, *pWqT, *pU, *pW2;
    float *pKV, *pS;
    cudaGetSymbolAddress((void**)&pH16,  g_h16);
    cudaGetSymbolAddress((void**)&pWkvh, g_Wkvh);
    cudaGetSymbolAddress((void**)&pWqT,  g_WqT);
    cudaGetSymbolAddress((void**)&pU,    g_U);
    cudaGetSymbolAddress((void**)&pW2,   g_W2);
    cudaGetSymbolAddress((void**)&pKV,   g_KV);
    cudaGetSymbolAddress((void**)&pS,    g_S);

    cudaFuncSetAttribute(gemm_fp16,
                         cudaFuncAttributeMaxDynamicSharedMemorySize, GSMEM);

    // 1) conversions: h -> fp16, [Wk;Wv] -> fp16, Wq^T -> fp16
    cvt16_kernel<<<ROWS, 256>>>(h, pH16);
    cvtw_kernel<<<2 * HID, 256>>>(Wk, Wv, pWkvh);
    cvtwqT_kernel<<<dim3(32, 32), dim3(32, 8)>>>(Wq, pWqT);

    // 2) KV projection: [K | V] fp32
    gemm_fp16<<<dim3(16, ROWS / 128), 256, GSMEM>>>(
        pH16, pWkvh, pKV, 2048, nullptr, 0, 0);

    // 3) S = K^T V per (b,h);  U_b = S_h * Wo_h^T (fp16, A-layout)
    cudaMemsetAsync(pS, 0, (size_t)BATCH * NHEAD * HDIM * HDIM * sizeof(float));
    ktv_kernel<<<dim3(BATCH * NHEAD, MSPLIT), 256>>>();
    u_kernel<<<dim3(BATCH * NHEAD, 8), 256>>>(Wo);

    // 4) W2_b[j][c] = sum_t U_b[t,j] * Wq[t,c]   (fp16 out, B-layout)
    gemm_fp16<<<dim3(8, (BATCH * HID) / 128), 256, GSMEM>>>(
        pU, pWqT, nullptr, 0, pW2, 1, 0);

    // 5) out = h16 @ W2_b^T  (per-batch B via bstride)
    gemm_fp16<<<dim3(8, ROWS / 128), 256, GSMEM>>>(
        pH16, pW2, out, 1024, nullptr, 0, (size_t)HID * HID);
}

// round 9
// speedup vs baseline: 2.7667x; 1.0936x over previous
#include <cuda_runtime.h>
#include <cuda_fp16.h>
#include <cstdint>

// Problem constants
#define BATCH 2
#define SEQ   2048
#define HID   1024
#define NHEAD 16
#define HDIM  64
#define ROWS  (BATCH * SEQ)      // 4096
#define NIT   32                 // 32 k-chunks of 32 (K = 1024)

// ---------------- scratch (static device allocations; no cudaMalloc) --------
__device__ __half g_h16 [ROWS * HID];       // h fp16 (A for GEMM1 and GEMM2)
__device__ __half g_Wkvh[2048 * HID];       // [Wk;Wv] fp16 (B layout)
__device__ __half g_WqT [HID * HID];        // Wq^T fp16: [c][t] = Wq[t][c]
__device__ float  g_KV  [ROWS * 2048];      // [K | V] projections, fp32
__device__ __half g_U   [BATCH * HID * HID];// g_U[b*1024+j][t] = U_b[t,j]
__device__ __half g_W2  [BATCH * HID * HID];// W2_b[j][c] (B layout for GEMM2)
__device__ float  g_S   [BATCH * NHEAD * HDIM * HDIM];

// ---------------- helpers ----------------------------------------------------
__device__ __forceinline__ uint32_t smem_u32(const void* p) {
    uint32_t a;
    asm("{ .reg .u64 t; cvta.to.shared.u64 t, %1; cvt.u32.u64 %0, t; }"
        : "=r"(a) : "l"(p));
    return a;
}
__device__ __forceinline__ void cp16(uint32_t dst, const void* src) {
    asm volatile("cp.async.cg.shared.global [%0], [%1], 16;"
                 :: "r"(dst), "l"(src));
}

// ---- convert fp32 -> fp16 (flat) --------------------------------------------
__global__ void cvt16_kernel(const float* __restrict__ X,
                             __half* __restrict__ Y) {
    size_t i = (size_t)blockIdx.x * 256 + threadIdx.x;
    float4 v = *(const float4*)(X + i * 4);
    unsigned s0 = __half_as_ushort(__float2half_rn(v.x));
    unsigned s1 = __half_as_ushort(__float2half_rn(v.y));
    unsigned s2 = __half_as_ushort(__float2half_rn(v.z));
    unsigned s3 = __half_as_ushort(__float2half_rn(v.w));
    *(uint2*)((unsigned short*)Y + i * 4) =
        make_uint2(s0 | (s1 << 16), s2 | (s3 << 16));
}

// ---- fused: Wk,Wv -> g_Wkvh -------------------------------------------------
__global__ void cvtw_kernel(const float* __restrict__ Wk,
                            const float* __restrict__ Wv,
                            __half* __restrict__ Y) {
    int blk = blockIdx.x;               // 0..2047, one row each
    int sel = blk >> 10;                // 0..1
    int row = blk & 1023;
    const float* src = (sel == 0) ? Wk : Wv;
    __half* dst = Y + ((size_t)sel * HID + row) * HID;
    int c4 = threadIdx.x * 4;
    float4 v = *(const float4*)(src + (size_t)row * HID + c4);
    unsigned s0 = __half_as_ushort(__float2half_rn(v.x));
    unsigned s1 = __half_as_ushort(__float2half_rn(v.y));
    unsigned s2 = __half_as_ushort(__float2half_rn(v.z));
    unsigned s3 = __half_as_ushort(__float2half_rn(v.w));
    *(uint2*)((unsigned short*)dst + c4) =
        make_uint2(s0 | (s1 << 16), s2 | (s3 << 16));
}

// ---- transpose + convert: WqT[c][t] = fp16(Wq[t][c]) ------------------------
__global__ void cvtwqT_kernel(const float* __restrict__ Wq,
                              __half* __restrict__ WqT) {
    __shared__ float tile[32][33];
    int bx = blockIdx.x * 32, by = blockIdx.y * 32;
    int tx = threadIdx.x, ty = threadIdx.y;   // (32, 8)
#pragma unroll
    for (int i = 0; i < 32; i += 8)
        tile[ty + i][tx] = Wq[(size_t)(by + ty + i) * HID + bx + tx];
    __syncthreads();
#pragma unroll
    for (int i = 0; i < 32; i += 8)
        WqT[(size_t)(bx + ty + i) * HID + by + tx] =
            __float2half_rn(tile[tx][ty + i]);
}

// ---------------- fp16 GEMM via mma.sync (m16n8k16), K = 1024 ---------------
// C = A[Mx1024] x B[Nx1024]^T. Tile 128x128, 16 warps (4m x 4n), warp tile
// 32x32, 4-stage cp.async (3 in flight). Smem rows padded to 80B ->
// conflict-free ldmatrix. fp16out -> Ch (ld 1024); else fp32 -> Cf (ld ldc).
// B pointer advanced by bstride elements per 2048-row batch.
#define LDB    80
#define ASZ    10240
#define STAGE  20480
#define NSTG   4
#define GSMEM  (NSTG * STAGE)    // 81920
#define ROWB   2048              // gmem row stride bytes (1024 fp16)

__global__ __launch_bounds__(512, 2)
void gemm_fp16(const __half* __restrict__ A,
               const __half* __restrict__ B,
               float* __restrict__ Cf, int ldc,
               __half* __restrict__ Ch, int fp16out, size_t bstride) {
    extern __shared__ char sm[];
    const int tid = threadIdx.x, lane = tid & 31, wid = tid >> 5;
    const int wm = wid & 3, wn = wid >> 2;
    const int bm = blockIdx.y * 128, bn = blockIdx.x * 128;
    const uint32_t sb = smem_u32(sm);
    const char* Ag = (const char*)A + (size_t)bm * ROWB;
    const char* Bg = (const char*)(B + (size_t)(bm >> 11) * bstride) +
                     (size_t)bn * ROWB;

    float acc[2][4][4];
#pragma unroll
    for (int mt = 0; mt < 2; ++mt)
#pragma unroll
        for (int nt = 0; nt < 4; ++nt)
#pragma unroll
            for (int j = 0; j < 4; ++j) acc[mt][nt][j] = 0.0f;

    const int lr = tid >> 2, lc = (tid & 3) * 16;   // 128 rows, 4x16B each

    auto load_stage = [&](int it) {
        int s = it & (NSTG - 1);
        int kb = (it & 31) * 64;
        uint32_t da = sb + s * STAGE, db = da + ASZ;
        cp16(da + lr * LDB + lc, Ag + kb + (size_t)lr * ROWB + lc);
        cp16(db + lr * LDB + lc, Bg + kb + (size_t)lr * ROWB + lc);
        asm volatile("cp.async.commit_group;" ::: "memory");
    };

    load_stage(0);
    load_stage(1);
    load_stage(2);

    for (int it = 0; it < NIT; ++it) {
        if (it < NIT - 1) asm volatile("cp.async.wait_group 2;" ::: "memory");
        else              asm volatile("cp.async.wait_group 0;" ::: "memory");
        __syncthreads();
        if (it + 3 < NIT) load_stage(it + 3);

        int s = it & (NSTG - 1);
        uint32_t abase = sb + s * STAGE +
                         (wm * 32 + (lane & 15)) * LDB + ((lane >> 4) & 1) * 16;
        uint32_t bbase = sb + s * STAGE + ASZ +
                         (wn * 32 + (lane & 7) + ((lane >> 3) & 1) * 8) * LDB +
                         ((lane >> 4) & 1) * 16;
#pragma unroll
        for (int ks = 0; ks < 2; ++ks) {
            uint32_t a[2][4], b[4][2];
#pragma unroll
            for (int mt = 0; mt < 2; ++mt)
                asm volatile(
                    "ldmatrix.sync.aligned.m8n8.x4.shared.b16 {%0,%1,%2,%3}, [%4];"
                    : "=r"(a[mt][0]), "=r"(a[mt][1]), "=r"(a[mt][2]), "=r"(a[mt][3])
                    : "r"(abase + ks * 32 + mt * (16 * LDB)));
#pragma unroll
            for (int g = 0; g < 2; ++g)
                asm volatile(
                    "ldmatrix.sync.aligned.m8n8.x4.shared.b16 {%0,%1,%2,%3}, [%4];"
                    : "=r"(b[2 * g][0]), "=r"(b[2 * g + 1][0]),
                      "=r"(b[2 * g][1]), "=r"(b[2 * g + 1][1])
                    : "r"(bbase + ks * 32 + g * (16 * LDB)));
#pragma unroll
            for (int mt = 0; mt < 2; ++mt)
#pragma unroll
                for (int nt = 0; nt < 4; ++nt)
                    asm volatile(
                        "mma.sync.aligned.m16n8k16.row.col.f32.f16.f16.f32 "
                        "{%0,%1,%2,%3}, {%4,%5,%6,%7}, {%8,%9}, {%0,%1,%2,%3};"
                        : "+f"(acc[mt][nt][0]), "+f"(acc[mt][nt][1]),
                          "+f"(acc[mt][nt][2]), "+f"(acc[mt][nt][3])
                        : "r"(a[mt][0]), "r"(a[mt][1]), "r"(a[mt][2]), "r"(a[mt][3]),
                          "r"(b[nt][0]), "r"(b[nt][1]));
        }
    }

    if (fp16out) {
#pragma unroll
        for (int mt = 0; mt < 2; ++mt)
#pragma unroll
            for (int nt = 0; nt < 4; ++nt) {
                int r0 = bm + wm * 32 + mt * 16 + (lane >> 2);
                int c0 = bn + wn * 32 + nt * 8 + (lane & 3) * 2;
                *(__half2*)(Ch + (size_t)r0 * HID + c0) =
                    __floats2half2_rn(acc[mt][nt][0], acc[mt][nt][1]);
                *(__half2*)(Ch + (size_t)(r0 + 8) * HID + c0) =
                    __floats2half2_rn(acc[mt][nt][2], acc[mt][nt][3]);
            }
    } else {
#pragma unroll
        for (int mt = 0; mt < 2; ++mt)
#pragma unroll
            for (int nt = 0; nt < 4; ++nt) {
                int r0 = bm + wm * 32 + mt * 16 + (lane >> 2);
                int c0 = bn + wn * 32 + nt * 8 + (lane & 3) * 2;
                *(float2*)(Cf + (size_t)r0 * ldc + c0) =
                    make_float2(acc[mt][nt][0], acc[mt][nt][1]);
                *(float2*)(Cf + (size_t)(r0 + 8) * ldc + c0) =
                    make_float2(acc[mt][nt][2], acc[mt][nt][3]);
            }
    }
}

// ---------------- S[b,h] = K_h^T @ V_h  (64x64, reduce over SEQ) ------------
#define MSPLIT 32
#define MCHUNK (SEQ / MSPLIT)   // 64
#define KVLD   2048             // g_KV row stride (floats)

__global__ __launch_bounds__(256)
void ktv_kernel() {
    const int bh = blockIdx.x;
    const int b  = bh / NHEAD;
    const int h  = bh % NHEAD;
    const int mbase = blockIdx.y * MCHUNK;

    __shared__ float Ks[16][HDIM];
    __shared__ float Vs[16][HDIM];

    const int tid = threadIdx.x;
    const int t1 = (tid >> 4) * 4;
    const int t2 = (tid & 15) * 4;

    const float* Kb = g_KV + ((size_t)b * SEQ) * KVLD + h * HDIM;
    const float* Vb = g_KV + ((size_t)b * SEQ) * KVLD + 1024 + h * HDIM;

    float acc[4][4];
#pragma unroll
    for (int i = 0; i < 4; ++i)
#pragma unroll
        for (int j = 0; j < 4; ++j) acc[i][j] = 0.0f;

    const int lrow = tid >> 4;
    const int lc4  = (tid & 15) * 4;

#pragma unroll
    for (int mc = 0; mc < MCHUNK / 16; ++mc) {
        int m0 = mbase + mc * 16;
        float4 kv = *(const float4*)(Kb + (size_t)(m0 + lrow) * KVLD + lc4);
        float4 vv = *(const float4*)(Vb + (size_t)(m0 + lrow) * KVLD + lc4);
        *(float4*)&Ks[lrow][lc4] = kv;
        *(float4*)&Vs[lrow][lc4] = vv;
        __syncthreads();
#pragma unroll
        for (int m = 0; m < 16; ++m) {
            float a[4], v[4];
#pragma unroll
            for (int i = 0; i < 4; ++i) a[i] = Ks[m][t1 + i];
#pragma unroll
            for (int j = 0; j < 4; ++j) v[j] = Vs[m][t2 + j];
#pragma unroll
            for (int i = 0; i < 4; ++i)
#pragma unroll
                for (int j = 0; j < 4; ++j)
                    acc[i][j] = fmaf(a[i], v[j], acc[i][j]);
        }
        __syncthreads();
    }

    float* Sb = g_S + (size_t)bh * HDIM * HDIM;
#pragma unroll
    for (int i = 0; i < 4; ++i)
#pragma unroll
        for (int j = 0; j < 4; ++j)
            atomicAdd(&Sb[(t1 + i) * HDIM + t2 + j], acc[i][j]);
}

// ---- g_U[b*1024+j][h*64+e] = sum_d S_h[e,d]*Wo[j,h*64+d]  (fp16) -----------
__global__ __launch_bounds__(256)
void u_kernel(const float* __restrict__ Wo) {
    const int bh = blockIdx.x;
    const int b  = bh / NHEAD;
    const int h  = bh % NHEAD;
    const int jbase = blockIdx.y * 128;

    __shared__ float Ss[HDIM][HDIM + 1];
    const int tid = threadIdx.x;
    {
        const float* Sb = g_S + (size_t)bh * HDIM * HDIM;
#pragma unroll
        for (int it = 0; it < 4; ++it) {
            int idx = tid + it * 256;
            int row = idx >> 4;
            int c4  = (idx & 15) * 4;
            float4 v = *(const float4*)(Sb + row * HDIM + c4);
            Ss[row][c4 + 0] = v.x; Ss[row][c4 + 1] = v.y;
            Ss[row][c4 + 2] = v.z; Ss[row][c4 + 3] = v.w;
        }
    }
    __syncthreads();

    const int jloc = tid >> 1;
    const int eh = (tid & 1) * 32;
    const int j = jbase + jloc;
    const float* wrow = Wo + (size_t)j * HID + h * HDIM;

    float acc[32];
#pragma unroll
    for (int e = 0; e < 32; ++e) acc[e] = 0.0f;

#pragma unroll
    for (int d4 = 0; d4 < HDIM; d4 += 4) {
        float4 w = *(const float4*)(wrow + d4);
#pragma unroll
        for (int e = 0; e < 32; ++e) {
            float s = fmaf(w.x, Ss[eh + e][d4 + 0],
                      fmaf(w.y, Ss[eh + e][d4 + 1],
                      fmaf(w.z, Ss[eh + e][d4 + 2],
                           w.w * Ss[eh + e][d4 + 3])));
            acc[e] += s;
        }
    }

    unsigned short* dst = (unsigned short*)g_U +
        ((size_t)b * HID + j) * HID + h * HDIM + eh;
#pragma unroll
    for (int q = 0; q < 4; ++q) {
        unsigned p[4];
#pragma unroll
        for (int t = 0; t < 4; ++t) {
            unsigned lo2 = __half_as_ushort(__float2half_rn(acc[q * 8 + t * 2]));
            unsigned hi2 = __half_as_ushort(__float2half_rn(acc[q * 8 + t * 2 + 1]));
            p[t] = lo2 | (hi2 << 16);
        }
        *(uint4*)(dst + q * 8) = make_uint4(p[0], p[1], p[2], p[3]);
    }
}

// ---------------- launch ----------------------------------------------------
extern "C" void kernel_launch(void* const* d_in, const int* in_sizes, int n_in,
                              void* d_out, int out_size) {
    (void)in_sizes; (void)n_in; (void)out_size;
    const float* h   = (const float*)d_in[0];
    const float* Wq  = (const float*)d_in[1];
    const float* Wk  = (const float*)d_in[2];
    const float* Wv  = (const float*)d_in[3];
    // d_in[4] = Wspan (dead code in reference)
    const float* Wo  = (const float*)d_in[5];
    float* out = (float*)d_out;

    __half *pH16, *pWkvh, *pWqT, *pU, *pW2;
    float *pKV, *pS;
    cudaGetSymbolAddress((void**)&pH16,  g_h16);
    cudaGetSymbolAddress((void**)&pWkvh, g_Wkvh);
    cudaGetSymbolAddress((void**)&pWqT,  g_WqT);
    cudaGetSymbolAddress((void**)&pU,    g_U);
    cudaGetSymbolAddress((void**)&pW2,   g_W2);
    cudaGetSymbolAddress((void**)&pKV,   g_KV);
    cudaGetSymbolAddress((void**)&pS,    g_S);

    cudaFuncSetAttribute(gemm_fp16,
                         cudaFuncAttributeMaxDynamicSharedMemorySize, GSMEM);

    // 1) conversions: h -> fp16, [Wk;Wv] -> fp16, Wq^T -> fp16
    cvt16_kernel<<<ROWS, 256>>>(h, pH16);
    cvtw_kernel<<<2 * HID, 256>>>(Wk, Wv, pWkvh);
    cvtwqT_kernel<<<dim3(32, 32), dim3(32, 8)>>>(Wq, pWqT);

    // 2) KV projection: [K | V] fp32
    gemm_fp16<<<dim3(16, ROWS / 128), 512, GSMEM>>>(
        pH16, pWkvh, pKV, 2048, nullptr, 0, 0);

    // 3) S = K^T V per (b,h);  U_b = S_h * Wo_h^T (fp16, A-layout)
    cudaMemsetAsync(pS, 0, (size_t)BATCH * NHEAD * HDIM * HDIM * sizeof(float));
    ktv_kernel<<<dim3(BATCH * NHEAD, MSPLIT), 256>>>();
    u_kernel<<<dim3(BATCH * NHEAD, 8), 256>>>(Wo);

    // 4) W2_b[j][c] = sum_t U_b[t,j] * Wq[t,c]   (fp16 out, B-layout)
    gemm_fp16<<<dim3(8, (BATCH * HID) / 128), 512, GSMEM>>>(
        pU, pWqT, nullptr, 0, pW2, 1, 0);

    // 5) out = h16 @ W2_b^T  (per-batch B via bstride)
    gemm_fp16<<<dim3(8, ROWS / 128), 512, GSMEM>>>(
        pH16, pW2, out, 1024, nullptr, 0, (size_t)HID * HID);
}